// round 14
// baseline (speedup 1.0000x reference)
#include <cuda_runtime.h>
#include <cuda_bf16.h>
#include <cuda_fp16.h>
#include <math.h>

#define NN 20000
#define NNP 20096
#define NE 640000
#define ET (NE + NN)
#define FH 4
#define CC 64
#define HC 256
#define SBLK 79   // ceil(NN/256)

// ---------------- device scratch ----------------
__device__ __half g_hh[NN * HC];
__device__ __half g_xh[NNP * 128];   // pad rows stay zero
__device__ __half g_x2h[NNP * HC];   // pad rows stay zero
__device__ float  g_as[NN * FH];
__device__ float  g_ad[NN * FH];
__device__ float  g_as2[NN * FH];
__device__ float  g_ad2[NN * FH];
__device__ int    g_gmax1[FH];
__device__ int    g_gmax2[FH];
__device__ int    g_deg[NN];
__device__ int    g_bsum[SBLK];
__device__ int    g_flag[SBLK];
__device__ int    g_rowptr[NN + 1];
__device__ int    g_fill[NN];
__device__ int    g_csr_src[ET];
__device__ __half g_bt1[256 * 128];
__device__ __half g_bt2[256 * 256];
__device__ float  g_wsd1[8 * 128];
__device__ float  g_wsd2[8 * 256];

__device__ __forceinline__ int enc_f(float f) {
    int i = __float_as_int(f);
    return i >= 0 ? i : (i ^ 0x7FFFFFFF);
}
__device__ __forceinline__ float dec_f(int u) {
    return __int_as_float(u >= 0 ? u : (u ^ 0x7FFFFFFF));
}

// ---------------- prep: weight transposes + wsd + deg/gmax/flag init, ONE launch ----------------
__global__ void prep_k(const float* __restrict__ W1, const float* __restrict__ atts1,
                       const float* __restrict__ attd1,
                       const float* __restrict__ W2, const float* __restrict__ atts2,
                       const float* __restrict__ attd2) {
    if (blockIdx.x < 384) {
        int i = blockIdx.x * 256 + threadIdx.x;
        if (i < 128 * 256) {
            int r = i >> 8, c = i & 255;
            g_bt1[c * 128 + r] = __float2half(W1[i]);
        } else {
            int j = i - 128 * 256;
            int r = j >> 8, c = j & 255;
            g_bt2[c * 256 + r] = __float2half(W2[j]);
        }
        return;
    }
    int t = (blockIdx.x - 384) * 256 + threadIdx.x;   // 0..3071
    if (t < 8) { g_gmax1[t] = (int)0x80000000; g_gmax2[t] = (int)0x80000000; }
    if (t == 8) g_rowptr[NN] = ET;                    // total is a constant
    for (int i = t; i < SBLK; i += 3072) g_flag[i] = 0;
    for (int i = t; i < NN; i += 3072) g_deg[i] = 1;  // self-loop pre-counted
    if (t < 1024) {
        int j = t >> 7, k = t & 127;
        int hd = j & 3;
        const float* av = (j < 4 ? atts1 : attd1) + hd * 64;
        const float* wr = W1 + k * 256 + hd * 64;
        float s = 0.f;
#pragma unroll 16
        for (int c = 0; c < 64; c++) s += wr[c] * av[c];
        g_wsd1[j * 128 + k] = s;
    } else {
        int t2 = t - 1024;
        int j = t2 >> 8, k = t2 & 255;
        int hd = j & 3;
        const float* av = (j < 4 ? atts2 : attd2) + hd * 64;
        const float* wr = W2 + k * 256 + hd * 64;
        float s = 0.f;
#pragma unroll 16
        for (int c = 0; c < 64; c++) s += wr[c] * av[c];
        g_wsd2[j * 256 + k] = s;
    }
}

// ---------------- single-pass scan with parallel aggregate lookback ----------------
// 79 blocks (one wave); block b publishes aggregate, threads t<b gather predecessors.
__global__ void scan_k() {
    __shared__ int sm[256];
    __shared__ int soff;
    int t = threadIdx.x, b = blockIdx.x;
    int i = b * 256 + t;
    int d = (i < NN) ? g_deg[i] : 0;
    sm[t] = d;
    if (t == 0) soff = 0;
    __syncthreads();
    for (int off = 1; off < 256; off <<= 1) {
        int v = (t >= off) ? sm[t - off] : 0;
        __syncthreads();
        sm[t] += v;
        __syncthreads();
    }
    int incl = sm[t];
    if (t == 255) {
        g_bsum[b] = incl;            // block aggregate
        __threadfence();
        atomicExch(&g_flag[b], 1);
    }
    // parallel lookback: thread t handles predecessor block t
    if (t < b) {
        while (atomicAdd(&g_flag[t], 0) == 0) {}
        __threadfence();
        atomicAdd(&soff, g_bsum[t]);
    }
    __syncthreads();
    if (i < NN) {
        int r = soff + incl - d;     // global exclusive prefix
        g_rowptr[i] = r;
        g_csr_src[r] = i;            // self-loop in slot 0 of the segment
        g_fill[i] = r + 1;
    }
}

#define QT ((NE + 3) / 4)
__global__ void scatter_k(const int* __restrict__ ei) {
    int t = blockIdx.x * blockDim.x + threadIdx.x;
    if (t >= QT) return;
#pragma unroll
    for (int r = 0; r < 4; r++) {
        int e = t + r * QT;
        if (e < NE) {
            int src = ei[e], dst = ei[NE + e];
            int p = atomicAdd(&g_fill[dst], 1);
            g_csr_src[p] = src;
        }
    }
}

// ---------------- as/ad layer 1 + fp16 convert + fused edge histogram ----------------
__global__ void asad1_k(const float* __restrict__ x, const float* __restrict__ wsdt,
                        const int* __restrict__ ei) {
    __shared__ int bmax[4];
    if (threadIdx.x < 4) bmax[threadIdx.x] = (int)0x80000000;
    int e = blockIdx.x * 256 + threadIdx.x;        // NE threads exactly
    int hd_dst = ei[NE + e];
    atomicAdd(&g_deg[hd_dst], 1);
    __syncthreads();
    int n = (blockIdx.x * 256 + threadIdx.x) >> 5;
    int lane = threadIdx.x & 31;
    float4 xv = *(const float4*)&x[n * 128 + lane * 4];
    {
        uint2 u;
        *(__half2*)&u.x = __floats2half2_rn(xv.x, xv.y);
        *(__half2*)&u.y = __floats2half2_rn(xv.z, xv.w);
        *(uint2*)&g_xh[n * 128 + lane * 4] = u;
    }
    float acc[8];
#pragma unroll
    for (int j = 0; j < 8; j++) {
        float4 w = *(const float4*)&wsdt[j * 128 + lane * 4];
        acc[j] = xv.x * w.x + xv.y * w.y + xv.z * w.z + xv.w * w.w;
    }
#pragma unroll
    for (int off = 16; off; off >>= 1)
#pragma unroll
        for (int j = 0; j < 8; j++) acc[j] += __shfl_xor_sync(0xffffffffu, acc[j], off);
    if (lane == 0) {
        *(float4*)&g_as[n * 4] = make_float4(acc[0], acc[1], acc[2], acc[3]);
        *(float4*)&g_ad[n * 4] = make_float4(acc[4], acc[5], acc[6], acc[7]);
#pragma unroll
        for (int j = 0; j < 4; j++) atomicMax(&bmax[j], enc_f(acc[j]));
    }
    __syncthreads();
    if (threadIdx.x < 4) atomicMax(&g_gmax1[threadIdx.x], bmax[threadIdx.x]);
}

// ---------------- 2-stage pipelined fp16 tensor-core GEMM ----------------
__device__ __forceinline__ void mma_f16(float* c, const unsigned* a, const unsigned* b) {
    asm volatile(
        "mma.sync.aligned.m16n8k16.row.col.f32.f16.f16.f32 "
        "{%0,%1,%2,%3}, {%4,%5,%6,%7}, {%8,%9}, {%0,%1,%2,%3};\n"
        : "+f"(c[0]), "+f"(c[1]), "+f"(c[2]), "+f"(c[3])
        : "r"(a[0]), "r"(a[1]), "r"(a[2]), "r"(a[3]), "r"(b[0]), "r"(b[1]));
}

template <int KP>
__global__ void mma_gemm_k(const __half* __restrict__ A,
                           const __half* __restrict__ BT,
                           __half* __restrict__ Ch, int M) {
    const int BM = 128, BN = 64, BK = 32, LD = 40;
    __shared__ __align__(16) __half As[2][BM * LD];
    __shared__ __align__(16) __half Bs[2][BN * LD];
    int t = threadIdx.x, lane = t & 31, wid = t >> 5;
    int wm = wid & 3, wn = wid >> 2;
    int bm = blockIdx.y * BM, bn = blockIdx.x * BN;
    float acc[2][4][4] = {};

    int ar = t >> 1, ac = (t & 1) * 16;
    int brow = t >> 2, bcol = (t & 3) * 8;

    auto load_tile = [&](int k0, int st) {
        const __half* ag = A + (size_t)(bm + ar) * KP + k0 + ac;
        unsigned sa = (unsigned)__cvta_generic_to_shared(&As[st][ar * LD + ac]);
        asm volatile("cp.async.ca.shared.global [%0], [%1], 16;\n" :: "r"(sa), "l"(ag) : "memory");
        asm volatile("cp.async.ca.shared.global [%0], [%1], 16;\n" :: "r"(sa + 16), "l"(ag + 8) : "memory");
        const __half* bg = BT + (size_t)(bn + brow) * KP + k0 + bcol;
        unsigned sb = (unsigned)__cvta_generic_to_shared(&Bs[st][brow * LD + bcol]);
        asm volatile("cp.async.ca.shared.global [%0], [%1], 16;\n" :: "r"(sb), "l"(bg) : "memory");
        asm volatile("cp.async.commit_group;\n" ::: "memory");
    };

    load_tile(0, 0);
    const int NT = KP / BK;
    for (int i = 0; i < NT; i++) {
        if (i + 1 < NT) {
            load_tile((i + 1) * BK, (i + 1) & 1);
            asm volatile("cp.async.wait_group 1;\n" ::: "memory");
        } else {
            asm volatile("cp.async.wait_group 0;\n" ::: "memory");
        }
        __syncthreads();
        int st = i & 1;
#pragma unroll
        for (int kk = 0; kk < BK; kk += 16) {
            unsigned af[2][4], bf[2][4];
#pragma unroll
            for (int mt = 0; mt < 2; mt++) {
                unsigned addr = (unsigned)__cvta_generic_to_shared(
                    &As[st][(wm * 32 + mt * 16 + (lane & 15)) * LD + kk + (lane >> 4) * 8]);
                asm volatile("ldmatrix.sync.aligned.m8n8.x4.shared.b16 {%0,%1,%2,%3}, [%4];\n"
                             : "=r"(af[mt][0]), "=r"(af[mt][1]), "=r"(af[mt][2]), "=r"(af[mt][3])
                             : "r"(addr));
            }
#pragma unroll
            for (int nb = 0; nb < 2; nb++) {
                int nr = wn * 32 + nb * 16 + (lane & 7) + ((lane >> 4) << 3);
                int kc = kk + ((lane >> 3) & 1) * 8;
                unsigned addr = (unsigned)__cvta_generic_to_shared(&Bs[st][nr * LD + kc]);
                asm volatile("ldmatrix.sync.aligned.m8n8.x4.shared.b16 {%0,%1,%2,%3}, [%4];\n"
                             : "=r"(bf[nb][0]), "=r"(bf[nb][1]), "=r"(bf[nb][2]), "=r"(bf[nb][3])
                             : "r"(addr));
            }
#pragma unroll
            for (int mt = 0; mt < 2; mt++)
#pragma unroll
                for (int nt = 0; nt < 4; nt++) {
                    unsigned bq[2] = { bf[nt >> 1][(nt & 1) * 2], bf[nt >> 1][(nt & 1) * 2 + 1] };
                    mma_f16(acc[mt][nt], af[mt], bq);
                }
        }
        __syncthreads();
    }

    int g = lane >> 2, tg = lane & 3;
#pragma unroll
    for (int mt = 0; mt < 2; mt++) {
        int r0 = bm + wm * 32 + mt * 16 + g;
#pragma unroll
        for (int nt = 0; nt < 4; nt++) {
            int c = bn + wn * 32 + nt * 8 + tg * 2;
            if (r0 < M)
                *(__half2*)&Ch[(size_t)r0 * 256 + c] = __floats2half2_rn(acc[mt][nt][0], acc[mt][nt][1]);
            if (r0 + 8 < M)
                *(__half2*)&Ch[(size_t)(r0 + 8) * 256 + c] = __floats2half2_rn(acc[mt][nt][2], acc[mt][nt][3]);
        }
    }
}

// ---------------- layer-1 aggregation + fused layer-2 logits ----------------
__global__ void agg1_k(const __half* __restrict__ hh, const float* __restrict__ bias,
                       const int* __restrict__ gmax, const float* __restrict__ wsd2) {
    __shared__ float ps[8][32][4];
    __shared__ float w2s[8 * 256];
    __shared__ int bmax[4];
    {
        int t = threadIdx.x;
        for (int i = t; i < 8 * 256; i += 256) w2s[i] = wsd2[i];
        if (t < 4) bmax[t] = (int)0x80000000;
        __syncthreads();
    }
    int n = (blockIdx.x * 256 + threadIdx.x) >> 5;
    int lane = threadIdx.x & 31;
    int w = threadIdx.x >> 5;
    int beg = g_rowptr[n], end = g_rowptr[n + 1];
    float4 ad4 = *(const float4*)&g_ad[n * 4];
    float m0 = dec_f(gmax[0]) + ad4.x; m0 = fmaxf(m0, 0.2f * m0);
    float m1 = dec_f(gmax[1]) + ad4.y; m1 = fmaxf(m1, 0.2f * m1);
    float m2 = dec_f(gmax[2]) + ad4.z; m2 = fmaxf(m2, 0.2f * m2);
    float m3 = dec_f(gmax[3]) + ad4.w; m3 = fmaxf(m3, 0.2f * m3);

    float a[8] = {};
    float s0 = 0.f, s1 = 0.f, s2 = 0.f, s3 = 0.f;
    int hd = lane >> 3;
    const __half* hp = hh + lane * 8;

    for (int base = beg; base < end; base += 32) {
        int i = base + lane;
        float p0 = 0.f, p1 = 0.f, p2 = 0.f, p3 = 0.f;
        int sj = 0;
        if (i < end) {
            sj = g_csr_src[i];
            float4 as4 = *(const float4*)&g_as[sj * 4];
            float e;
            e = as4.x + ad4.x; e = fmaxf(e, 0.2f * e); p0 = __expf(e - m0);
            e = as4.y + ad4.y; e = fmaxf(e, 0.2f * e); p1 = __expf(e - m1);
            e = as4.z + ad4.z; e = fmaxf(e, 0.2f * e); p2 = __expf(e - m2);
            e = as4.w + ad4.w; e = fmaxf(e, 0.2f * e); p3 = __expf(e - m3);
        }
        s0 += p0; s1 += p1; s2 += p2; s3 += p3;
        ps[w][lane][0] = p0; ps[w][lane][1] = p1;
        ps[w][lane][2] = p2; ps[w][lane][3] = p3;
        __syncwarp();
        int cnt = min(32, end - base);
#pragma unroll 8
        for (int j = 0; j < cnt; j++) {
            int sc = __shfl_sync(0xffffffffu, sj, j);
            float p = ps[w][j][hd];
            uint4 v = *(const uint4*)(hp + sc * HC);
            __half2* hv = (__half2*)&v;
            float2 f0 = __half22float2(hv[0]);
            float2 f1 = __half22float2(hv[1]);
            float2 f2 = __half22float2(hv[2]);
            float2 f3 = __half22float2(hv[3]);
            a[0] += p * f0.x; a[1] += p * f0.y;
            a[2] += p * f1.x; a[3] += p * f1.y;
            a[4] += p * f2.x; a[5] += p * f2.y;
            a[6] += p * f3.x; a[7] += p * f3.y;
        }
        __syncwarp();
    }
#pragma unroll
    for (int off = 16; off; off >>= 1) {
        s0 += __shfl_xor_sync(0xffffffffu, s0, off);
        s1 += __shfl_xor_sync(0xffffffffu, s1, off);
        s2 += __shfl_xor_sync(0xffffffffu, s2, off);
        s3 += __shfl_xor_sync(0xffffffffu, s3, off);
    }
    float sv = (hd == 0) ? s0 : (hd == 1) ? s1 : (hd == 2) ? s2 : s3;
    float inv = 1.f / sv;
    int ch = lane * 8;
    float4 bA = *(const float4*)&bias[ch];
    float4 bB = *(const float4*)&bias[ch + 4];
    float v[8];
    v[0] = a[0] * inv + bA.x; v[1] = a[1] * inv + bA.y;
    v[2] = a[2] * inv + bA.z; v[3] = a[3] * inv + bA.w;
    v[4] = a[4] * inv + bB.x; v[5] = a[5] * inv + bB.y;
    v[6] = a[6] * inv + bB.z; v[7] = a[7] * inv + bB.w;
#pragma unroll
    for (int t = 0; t < 8; t++) v[t] = (v[t] > 0.f) ? v[t] : (__expf(v[t]) - 1.f);
    {
        uint4 o;
        __half2* oh = (__half2*)&o;
        oh[0] = __floats2half2_rn(v[0], v[1]);
        oh[1] = __floats2half2_rn(v[2], v[3]);
        oh[2] = __floats2half2_rn(v[4], v[5]);
        oh[3] = __floats2half2_rn(v[6], v[7]);
        *(uint4*)&g_x2h[n * 256 + ch] = o;
    }
    float acc[8];
#pragma unroll
    for (int j = 0; j < 8; j++) {
        const float* wr = &w2s[j * 256 + ch];
        acc[j] = v[0] * wr[0] + v[1] * wr[1] + v[2] * wr[2] + v[3] * wr[3]
               + v[4] * wr[4] + v[5] * wr[5] + v[6] * wr[6] + v[7] * wr[7];
    }
#pragma unroll
    for (int off = 16; off; off >>= 1)
#pragma unroll
        for (int j = 0; j < 8; j++) acc[j] += __shfl_xor_sync(0xffffffffu, acc[j], off);
    if (lane == 0) {
        *(float4*)&g_as2[n * 4] = make_float4(acc[0], acc[1], acc[2], acc[3]);
        *(float4*)&g_ad2[n * 4] = make_float4(acc[4], acc[5], acc[6], acc[7]);
#pragma unroll
        for (int j = 0; j < 4; j++) atomicMax(&bmax[j], enc_f(acc[j]));
    }
    __syncthreads();
    if (threadIdx.x < 4) atomicMax(&g_gmax2[threadIdx.x], bmax[threadIdx.x]);
}

// ---------------- layer-2 aggregation + fused tail ----------------
__global__ void agg2_k(const __half* __restrict__ hh, const int* __restrict__ gmax,
                       const float* __restrict__ Wout, const float* __restrict__ bout,
                       const float* __restrict__ b2, float* __restrict__ out) {
    __shared__ float ps[8][32][4];
    __shared__ float msum[8][CC];
    __shared__ float Ws[CC * 16];
    __shared__ float b2s[CC];
    __shared__ float bouts[16];
    {
        int t = threadIdx.x;
        for (int i = t; i < CC * 16; i += 256) Ws[i] = Wout[i];
        if (t < CC) b2s[t] = b2[t];
        if (t < 16) bouts[t] = bout[t];
        __syncthreads();
    }
    int n = (blockIdx.x * 256 + threadIdx.x) >> 5;
    int lane = threadIdx.x & 31;
    int w = threadIdx.x >> 5;
    int beg = g_rowptr[n], end = g_rowptr[n + 1];
    float4 ad4 = *(const float4*)&g_ad2[n * 4];
    float m0 = dec_f(gmax[0]) + ad4.x; m0 = fmaxf(m0, 0.2f * m0);
    float m1 = dec_f(gmax[1]) + ad4.y; m1 = fmaxf(m1, 0.2f * m1);
    float m2 = dec_f(gmax[2]) + ad4.z; m2 = fmaxf(m2, 0.2f * m2);
    float m3 = dec_f(gmax[3]) + ad4.w; m3 = fmaxf(m3, 0.2f * m3);

    float a[8] = {};
    float s0 = 0.f, s1 = 0.f, s2 = 0.f, s3 = 0.f;
    int hd = lane >> 3;
    const __half* hp = hh + lane * 8;

    for (int base = beg; base < end; base += 32) {
        int i = base + lane;
        float p0 = 0.f, p1 = 0.f, p2 = 0.f, p3 = 0.f;
        int sj = 0;
        if (i < end) {
            sj = g_csr_src[i];
            float4 as4 = *(const float4*)&g_as2[sj * 4];
            float e;
            e = as4.x + ad4.x; e = fmaxf(e, 0.2f * e); p0 = __expf(e - m0);
            e = as4.y + ad4.y; e = fmaxf(e, 0.2f * e); p1 = __expf(e - m1);
            e = as4.z + ad4.z; e = fmaxf(e, 0.2f * e); p2 = __expf(e - m2);
            e = as4.w + ad4.w; e = fmaxf(e, 0.2f * e); p3 = __expf(e - m3);
        }
        s0 += p0; s1 += p1; s2 += p2; s3 += p3;
        ps[w][lane][0] = p0; ps[w][lane][1] = p1;
        ps[w][lane][2] = p2; ps[w][lane][3] = p3;
        __syncwarp();
        int cnt = min(32, end - base);
#pragma unroll 8
        for (int j = 0; j < cnt; j++) {
            int sc = __shfl_sync(0xffffffffu, sj, j);
            float p = ps[w][j][hd];
            uint4 v = *(const uint4*)(hp + sc * HC);
            __half2* hv = (__half2*)&v;
            float2 f0 = __half22float2(hv[0]);
            float2 f1 = __half22float2(hv[1]);
            float2 f2 = __half22float2(hv[2]);
            float2 f3 = __half22float2(hv[3]);
            a[0] += p * f0.x; a[1] += p * f0.y;
            a[2] += p * f1.x; a[3] += p * f1.y;
            a[4] += p * f2.x; a[5] += p * f2.y;
            a[6] += p * f3.x; a[7] += p * f3.y;
        }
        __syncwarp();
    }
#pragma unroll
    for (int off = 16; off; off >>= 1) {
        s0 += __shfl_xor_sync(0xffffffffu, s0, off);
        s1 += __shfl_xor_sync(0xffffffffu, s1, off);
        s2 += __shfl_xor_sync(0xffffffffu, s2, off);
        s3 += __shfl_xor_sync(0xffffffffu, s3, off);
    }
    float sv = (hd == 0) ? s0 : (hd == 1) ? s1 : (hd == 2) ? s2 : s3;
    float inv = 1.f / sv;
#pragma unroll
    for (int t = 0; t < 8; t++) a[t] *= inv;
#pragma unroll
    for (int off = 8; off <= 16; off <<= 1)
#pragma unroll
        for (int t = 0; t < 8; t++) a[t] += __shfl_xor_sync(0xffffffffu, a[t], off);
    if (lane < 8) {
        int cw = 8 * lane;
#pragma unroll
        for (int t = 0; t < 8; t++) msum[w][cw + t] = a[t] * 0.25f + b2s[cw + t];
    }
    __syncwarp();
    if (lane < 16) {
        float o = 0.f;
#pragma unroll 16
        for (int c = 0; c < CC; c++) o += msum[w][c] * Ws[c * 16 + lane];
        out[n * 16 + lane] = o + bouts[lane];
    }
}

// ---------------- launch (single stream, 8 launches) ----------------
extern "C" void kernel_launch(void* const* d_in, const int* in_sizes, int n_in,
                              void* d_out, int out_size) {
    const float* x     = (const float*)d_in[0];
    const int*   ei    = (const int*)d_in[1];
    const float* W1    = (const float*)d_in[2];
    const float* atts1 = (const float*)d_in[3];
    const float* attd1 = (const float*)d_in[4];
    const float* b1    = (const float*)d_in[5];
    const float* W2    = (const float*)d_in[6];
    const float* atts2 = (const float*)d_in[7];
    const float* attd2 = (const float*)d_in[8];
    const float* b2    = (const float*)d_in[9];
    const float* Wout  = (const float*)d_in[10];
    const float* bout  = (const float*)d_in[11];
    float* out = (float*)d_out;

    __half* ghh;   cudaGetSymbolAddress((void**)&ghh, g_hh);
    __half* gxh;   cudaGetSymbolAddress((void**)&gxh, g_xh);
    __half* gx2h;  cudaGetSymbolAddress((void**)&gx2h, g_x2h);
    __half* gbt1;  cudaGetSymbolAddress((void**)&gbt1, g_bt1);
    __half* gbt2;  cudaGetSymbolAddress((void**)&gbt2, g_bt2);
    float* gwsd1;  cudaGetSymbolAddress((void**)&gwsd1, g_wsd1);
    float* gwsd2;  cudaGetSymbolAddress((void**)&gwsd2, g_wsd2);
    int* ggm1;     cudaGetSymbolAddress((void**)&ggm1, g_gmax1);
    int* ggm2;     cudaGetSymbolAddress((void**)&ggm2, g_gmax2);

    prep_k<<<396, 256>>>(W1, atts1, attd1, W2, atts2, attd2);
    asad1_k<<<NN / 8, 256>>>(x, gwsd1, ei);      // logits + fp16 x + edge histogram
    mma_gemm_k<128><<<dim3(4, NNP / 128), 256>>>(gxh, gbt1, ghh, NN);
    scan_k<<<SBLK, 256>>>();                     // single-pass scan + self-loops
    scatter_k<<<(QT + 255) / 256, 256>>>(ei);    // real edges only

    agg1_k<<<NN / 8, 256>>>(ghh, b1, ggm1, gwsd2);

    mma_gemm_k<256><<<dim3(4, NNP / 128), 256>>>(gx2h, gbt2, ghh, NN);
    agg2_k<<<NN / 8, 256>>>(ghh, ggm2, Wout, bout, b2, out);
}

// round 15
// speedup vs baseline: 1.2167x; 1.2167x over previous
#include <cuda_runtime.h>
#include <cuda_bf16.h>
#include <cuda_fp16.h>
#include <math.h>

#define NN 20000
#define NNP 20096
#define NE 640000
#define ET (NE + NN)
#define FH 4
#define CC 64
#define HC 256
#define SBLK 79   // ceil(NN/256)

// ---------------- device scratch ----------------
__device__ __half g_hh[NN * HC];     // layer-1 features fp16 (agg1 gather)
__device__ __half g_xh[NNP * 128];   // fp16 x (GEMM1 A); pad rows stay zero
__device__ __half g_x2h[NNP * HC];   // fp16 elu(agg1+b1) (GEMM-z A); pad rows zero
__device__ float  g_z[NNP * 64];     // z = x2 @ W2z  (fp32, agg2 gather)
__device__ float  g_as[NN * FH];
__device__ float  g_ad[NN * FH];
__device__ float  g_as2[NN * FH];
__device__ float  g_ad2[NN * FH];
__device__ int    g_gmax1[FH];
__device__ int    g_gmax2[FH];
__device__ int    g_deg[NN];
__device__ int    g_bsum[SBLK];
__device__ int    g_flag[SBLK];
__device__ int    g_rowptr[NN + 1];
__device__ int    g_fill[NN];
__device__ int    g_csr_src[ET];
__device__ __half g_bt1[256 * 128];  // W1^T fp16
__device__ __half g_btz[64 * 256];   // (W2 @ blockdiag(Wout))^T fp16
__device__ float  g_wsd1[8 * 128];
__device__ float  g_wsd2[8 * 256];
__device__ float  g_cvec[16];        // b2 @ Wout + bout

__device__ __forceinline__ int enc_f(float f) {
    int i = __float_as_int(f);
    return i >= 0 ? i : (i ^ 0x7FFFFFFF);
}
__device__ __forceinline__ float dec_f(int u) {
    return __int_as_float(u >= 0 ? u : (u ^ 0x7FFFFFFF));
}

// ---------------- prep: bt1 + btz + wsd + cvec + deg/gmax/flag init, ONE launch ----------------
// blocks 0..127: W1 transpose; 128..191: W2z build+transpose; 192..203: wsd/init/cvec
__global__ void prep_k(const float* __restrict__ W1, const float* __restrict__ atts1,
                       const float* __restrict__ attd1,
                       const float* __restrict__ W2, const float* __restrict__ atts2,
                       const float* __restrict__ attd2,
                       const float* __restrict__ Wout, const float* __restrict__ b2,
                       const float* __restrict__ bout) {
    if (blockIdx.x < 128) {
        int i = blockIdx.x * 256 + threadIdx.x;     // 32768 = 128*256 elements
        int r = i >> 8, c = i & 255;
        g_bt1[c * 128 + r] = __float2half(W1[i]);
        return;
    }
    if (blockIdx.x < 192) {
        int i = (blockIdx.x - 128) * 256 + threadIdx.x;   // 16384 outputs
        int r = i >> 6, j = i & 63;                 // r: K-row 0..255, j: out col 0..63
        int hd = j >> 4, k = j & 15;
        const float* w2r = W2 + r * 256 + hd * 64;
        const float* wo = Wout + k;
        float s = 0.f;
#pragma unroll 16
        for (int c = 0; c < 64; c++) s += w2r[c] * wo[c * 16];
        g_btz[j * 256 + r] = __float2half(s);
        return;
    }
    int t = (blockIdx.x - 192) * 256 + threadIdx.x;   // 0..3071
    if (t < 8) { g_gmax1[t] = (int)0x80000000; g_gmax2[t] = (int)0x80000000; }
    if (t == 8) g_rowptr[NN] = ET;
    if (t < 16) {
        float s = bout[t];
#pragma unroll 16
        for (int c = 0; c < 64; c++) s += b2[c] * Wout[c * 16 + t];
        g_cvec[t] = s;
    }
    for (int i = t; i < SBLK; i += 3072) g_flag[i] = 0;
    for (int i = t; i < NN; i += 3072) g_deg[i] = 1;  // self-loop pre-counted
    if (t < 1024) {
        int j = t >> 7, k = t & 127;
        int hd = j & 3;
        const float* av = (j < 4 ? atts1 : attd1) + hd * 64;
        const float* wr = W1 + k * 256 + hd * 64;
        float s = 0.f;
#pragma unroll 16
        for (int c = 0; c < 64; c++) s += wr[c] * av[c];
        g_wsd1[j * 128 + k] = s;
    } else {
        int t2 = t - 1024;
        int j = t2 >> 8, k = t2 & 255;
        int hd = j & 3;
        const float* av = (j < 4 ? atts2 : attd2) + hd * 64;
        const float* wr = W2 + k * 256 + hd * 64;
        float s = 0.f;
#pragma unroll 16
        for (int c = 0; c < 64; c++) s += wr[c] * av[c];
        g_wsd2[j * 256 + k] = s;
    }
}

// ---------------- single-pass scan with parallel aggregate lookback ----------------
__global__ void scan_k() {
    __shared__ int sm[256];
    __shared__ int soff;
    int t = threadIdx.x, b = blockIdx.x;
    int i = b * 256 + t;
    int d = (i < NN) ? g_deg[i] : 0;
    sm[t] = d;
    if (t == 0) soff = 0;
    __syncthreads();
    for (int off = 1; off < 256; off <<= 1) {
        int v = (t >= off) ? sm[t - off] : 0;
        __syncthreads();
        sm[t] += v;
        __syncthreads();
    }
    int incl = sm[t];
    if (t == 255) {
        g_bsum[b] = incl;
        __threadfence();
        atomicExch(&g_flag[b], 1);
    }
    if (t < b) {
        while (atomicAdd(&g_flag[t], 0) == 0) {}
        __threadfence();
        atomicAdd(&soff, g_bsum[t]);
    }
    __syncthreads();
    if (i < NN) {
        int r = soff + incl - d;
        g_rowptr[i] = r;
        g_csr_src[r] = i;            // self-loop in slot 0
        g_fill[i] = r + 1;
    }
}

#define QT ((NE + 3) / 4)
__global__ void scatter_k(const int* __restrict__ ei) {
    int t = blockIdx.x * blockDim.x + threadIdx.x;
    if (t >= QT) return;
#pragma unroll
    for (int r = 0; r < 4; r++) {
        int e = t + r * QT;
        if (e < NE) {
            int src = ei[e], dst = ei[NE + e];
            int p = atomicAdd(&g_fill[dst], 1);
            g_csr_src[p] = src;
        }
    }
}

// ---------------- as/ad layer 1 + fp16 convert + fused edge histogram ----------------
__global__ void asad1_k(const float* __restrict__ x, const float* __restrict__ wsdt,
                        const int* __restrict__ ei) {
    __shared__ int bmax[4];
    if (threadIdx.x < 4) bmax[threadIdx.x] = (int)0x80000000;
    int e = blockIdx.x * 256 + threadIdx.x;        // NE threads exactly
    int hd_dst = ei[NE + e];
    atomicAdd(&g_deg[hd_dst], 1);
    __syncthreads();
    int n = (blockIdx.x * 256 + threadIdx.x) >> 5;
    int lane = threadIdx.x & 31;
    float4 xv = *(const float4*)&x[n * 128 + lane * 4];
    {
        uint2 u;
        *(__half2*)&u.x = __floats2half2_rn(xv.x, xv.y);
        *(__half2*)&u.y = __floats2half2_rn(xv.z, xv.w);
        *(uint2*)&g_xh[n * 128 + lane * 4] = u;
    }
    float acc[8];
#pragma unroll
    for (int j = 0; j < 8; j++) {
        float4 w = *(const float4*)&wsdt[j * 128 + lane * 4];
        acc[j] = xv.x * w.x + xv.y * w.y + xv.z * w.z + xv.w * w.w;
    }
#pragma unroll
    for (int off = 16; off; off >>= 1)
#pragma unroll
        for (int j = 0; j < 8; j++) acc[j] += __shfl_xor_sync(0xffffffffu, acc[j], off);
    if (lane == 0) {
        *(float4*)&g_as[n * 4] = make_float4(acc[0], acc[1], acc[2], acc[3]);
        *(float4*)&g_ad[n * 4] = make_float4(acc[4], acc[5], acc[6], acc[7]);
#pragma unroll
        for (int j = 0; j < 4; j++) atomicMax(&bmax[j], enc_f(acc[j]));
    }
    __syncthreads();
    if (threadIdx.x < 4) atomicMax(&g_gmax1[threadIdx.x], bmax[threadIdx.x]);
}

// ---------------- 2-stage pipelined fp16 tensor-core GEMM ----------------
// OUTF32: write fp32 to Cf (N=NOUT), else fp16 to Ch
__device__ __forceinline__ void mma_f16(float* c, const unsigned* a, const unsigned* b) {
    asm volatile(
        "mma.sync.aligned.m16n8k16.row.col.f32.f16.f16.f32 "
        "{%0,%1,%2,%3}, {%4,%5,%6,%7}, {%8,%9}, {%0,%1,%2,%3};\n"
        : "+f"(c[0]), "+f"(c[1]), "+f"(c[2]), "+f"(c[3])
        : "r"(a[0]), "r"(a[1]), "r"(a[2]), "r"(a[3]), "r"(b[0]), "r"(b[1]));
}

template <int KP, int NOUT, bool OUTF32>
__global__ void mma_gemm_k(const __half* __restrict__ A,
                           const __half* __restrict__ BT,
                           __half* __restrict__ Ch, float* __restrict__ Cf, int M) {
    const int BM = 128, BN = 64, BK = 32, LD = 40;
    __shared__ __align__(16) __half As[2][BM * LD];
    __shared__ __align__(16) __half Bs[2][BN * LD];
    int t = threadIdx.x, lane = t & 31, wid = t >> 5;
    int wm = wid & 3, wn = wid >> 2;
    int bm = blockIdx.y * BM, bn = blockIdx.x * BN;
    float acc[2][4][4] = {};

    int ar = t >> 1, ac = (t & 1) * 16;
    int brow = t >> 2, bcol = (t & 3) * 8;

    auto load_tile = [&](int k0, int st) {
        const __half* ag = A + (size_t)(bm + ar) * KP + k0 + ac;
        unsigned sa = (unsigned)__cvta_generic_to_shared(&As[st][ar * LD + ac]);
        asm volatile("cp.async.ca.shared.global [%0], [%1], 16;\n" :: "r"(sa), "l"(ag) : "memory");
        asm volatile("cp.async.ca.shared.global [%0], [%1], 16;\n" :: "r"(sa + 16), "l"(ag + 8) : "memory");
        const __half* bg = BT + (size_t)(bn + brow) * KP + k0 + bcol;
        unsigned sb = (unsigned)__cvta_generic_to_shared(&Bs[st][brow * LD + bcol]);
        asm volatile("cp.async.ca.shared.global [%0], [%1], 16;\n" :: "r"(sb), "l"(bg) : "memory");
        asm volatile("cp.async.commit_group;\n" ::: "memory");
    };

    load_tile(0, 0);
    const int NT = KP / BK;
    for (int i = 0; i < NT; i++) {
        if (i + 1 < NT) {
            load_tile((i + 1) * BK, (i + 1) & 1);
            asm volatile("cp.async.wait_group 1;\n" ::: "memory");
        } else {
            asm volatile("cp.async.wait_group 0;\n" ::: "memory");
        }
        __syncthreads();
        int st = i & 1;
#pragma unroll
        for (int kk = 0; kk < BK; kk += 16) {
            unsigned af[2][4], bf[2][4];
#pragma unroll
            for (int mt = 0; mt < 2; mt++) {
                unsigned addr = (unsigned)__cvta_generic_to_shared(
                    &As[st][(wm * 32 + mt * 16 + (lane & 15)) * LD + kk + (lane >> 4) * 8]);
                asm volatile("ldmatrix.sync.aligned.m8n8.x4.shared.b16 {%0,%1,%2,%3}, [%4];\n"
                             : "=r"(af[mt][0]), "=r"(af[mt][1]), "=r"(af[mt][2]), "=r"(af[mt][3])
                             : "r"(addr));
            }
#pragma unroll
            for (int nb = 0; nb < 2; nb++) {
                int nr = wn * 32 + nb * 16 + (lane & 7) + ((lane >> 4) << 3);
                int kc = kk + ((lane >> 3) & 1) * 8;
                unsigned addr = (unsigned)__cvta_generic_to_shared(&Bs[st][nr * LD + kc]);
                asm volatile("ldmatrix.sync.aligned.m8n8.x4.shared.b16 {%0,%1,%2,%3}, [%4];\n"
                             : "=r"(bf[nb][0]), "=r"(bf[nb][1]), "=r"(bf[nb][2]), "=r"(bf[nb][3])
                             : "r"(addr));
            }
#pragma unroll
            for (int mt = 0; mt < 2; mt++)
#pragma unroll
                for (int nt = 0; nt < 4; nt++) {
                    unsigned bq[2] = { bf[nt >> 1][(nt & 1) * 2], bf[nt >> 1][(nt & 1) * 2 + 1] };
                    mma_f16(acc[mt][nt], af[mt], bq);
                }
        }
        __syncthreads();
    }

    int g = lane >> 2, tg = lane & 3;
#pragma unroll
    for (int mt = 0; mt < 2; mt++) {
        int r0 = bm + wm * 32 + mt * 16 + g;
#pragma unroll
        for (int nt = 0; nt < 4; nt++) {
            int c = bn + wn * 32 + nt * 8 + tg * 2;
            if (OUTF32) {
                if (r0 < M)
                    *(float2*)&Cf[(size_t)r0 * NOUT + c] = make_float2(acc[mt][nt][0], acc[mt][nt][1]);
                if (r0 + 8 < M)
                    *(float2*)&Cf[(size_t)(r0 + 8) * NOUT + c] = make_float2(acc[mt][nt][2], acc[mt][nt][3]);
            } else {
                if (r0 < M)
                    *(__half2*)&Ch[(size_t)r0 * NOUT + c] = __floats2half2_rn(acc[mt][nt][0], acc[mt][nt][1]);
                if (r0 + 8 < M)
                    *(__half2*)&Ch[(size_t)(r0 + 8) * NOUT + c] = __floats2half2_rn(acc[mt][nt][2], acc[mt][nt][3]);
            }
        }
    }
}

// ---------------- layer-1 aggregation + fused layer-2 logits ----------------
__global__ void agg1_k(const __half* __restrict__ hh, const float* __restrict__ bias,
                       const int* __restrict__ gmax, const float* __restrict__ wsd2) {
    __shared__ float ps[8][32][4];
    __shared__ float w2s[8 * 256];
    __shared__ int bmax[4];
    {
        int t = threadIdx.x;
        for (int i = t; i < 8 * 256; i += 256) w2s[i] = wsd2[i];
        if (t < 4) bmax[t] = (int)0x80000000;
        __syncthreads();
    }
    int n = (blockIdx.x * 256 + threadIdx.x) >> 5;
    int lane = threadIdx.x & 31;
    int w = threadIdx.x >> 5;
    int beg = g_rowptr[n], end = g_rowptr[n + 1];
    float4 ad4 = *(const float4*)&g_ad[n * 4];
    float m0 = dec_f(gmax[0]) + ad4.x; m0 = fmaxf(m0, 0.2f * m0);
    float m1 = dec_f(gmax[1]) + ad4.y; m1 = fmaxf(m1, 0.2f * m1);
    float m2 = dec_f(gmax[2]) + ad4.z; m2 = fmaxf(m2, 0.2f * m2);
    float m3 = dec_f(gmax[3]) + ad4.w; m3 = fmaxf(m3, 0.2f * m3);

    float a[8] = {};
    float s0 = 0.f, s1 = 0.f, s2 = 0.f, s3 = 0.f;
    int hd = lane >> 3;
    const __half* hp = hh + lane * 8;

    for (int base = beg; base < end; base += 32) {
        int i = base + lane;
        float p0 = 0.f, p1 = 0.f, p2 = 0.f, p3 = 0.f;
        int sj = 0;
        if (i < end) {
            sj = g_csr_src[i];
            float4 as4 = *(const float4*)&g_as[sj * 4];
            float e;
            e = as4.x + ad4.x; e = fmaxf(e, 0.2f * e); p0 = __expf(e - m0);
            e = as4.y + ad4.y; e = fmaxf(e, 0.2f * e); p1 = __expf(e - m1);
            e = as4.z + ad4.z; e = fmaxf(e, 0.2f * e); p2 = __expf(e - m2);
            e = as4.w + ad4.w; e = fmaxf(e, 0.2f * e); p3 = __expf(e - m3);
        }
        s0 += p0; s1 += p1; s2 += p2; s3 += p3;
        ps[w][lane][0] = p0; ps[w][lane][1] = p1;
        ps[w][lane][2] = p2; ps[w][lane][3] = p3;
        __syncwarp();
        int cnt = min(32, end - base);
#pragma unroll 8
        for (int j = 0; j < cnt; j++) {
            int sc = __shfl_sync(0xffffffffu, sj, j);
            float p = ps[w][j][hd];
            uint4 v = *(const uint4*)(hp + sc * HC);
            __half2* hv = (__half2*)&v;
            float2 f0 = __half22float2(hv[0]);
            float2 f1 = __half22float2(hv[1]);
            float2 f2 = __half22float2(hv[2]);
            float2 f3 = __half22float2(hv[3]);
            a[0] += p * f0.x; a[1] += p * f0.y;
            a[2] += p * f1.x; a[3] += p * f1.y;
            a[4] += p * f2.x; a[5] += p * f2.y;
            a[6] += p * f3.x; a[7] += p * f3.y;
        }
        __syncwarp();
    }
#pragma unroll
    for (int off = 16; off; off >>= 1) {
        s0 += __shfl_xor_sync(0xffffffffu, s0, off);
        s1 += __shfl_xor_sync(0xffffffffu, s1, off);
        s2 += __shfl_xor_sync(0xffffffffu, s2, off);
        s3 += __shfl_xor_sync(0xffffffffu, s3, off);
    }
    float sv = (hd == 0) ? s0 : (hd == 1) ? s1 : (hd == 2) ? s2 : s3;
    float inv = 1.f / sv;
    int ch = lane * 8;
    float4 bA = *(const float4*)&bias[ch];
    float4 bB = *(const float4*)&bias[ch + 4];
    float v[8];
    v[0] = a[0] * inv + bA.x; v[1] = a[1] * inv + bA.y;
    v[2] = a[2] * inv + bA.z; v[3] = a[3] * inv + bA.w;
    v[4] = a[4] * inv + bB.x; v[5] = a[5] * inv + bB.y;
    v[6] = a[6] * inv + bB.z; v[7] = a[7] * inv + bB.w;
#pragma unroll
    for (int t = 0; t < 8; t++) v[t] = (v[t] > 0.f) ? v[t] : (__expf(v[t]) - 1.f);
    {
        uint4 o;
        __half2* oh = (__half2*)&o;
        oh[0] = __floats2half2_rn(v[0], v[1]);
        oh[1] = __floats2half2_rn(v[2], v[3]);
        oh[2] = __floats2half2_rn(v[4], v[5]);
        oh[3] = __floats2half2_rn(v[6], v[7]);
        *(uint4*)&g_x2h[n * 256 + ch] = o;
    }
    float acc[8];
#pragma unroll
    for (int j = 0; j < 8; j++) {
        const float* wr = &w2s[j * 256 + ch];
        acc[j] = v[0] * wr[0] + v[1] * wr[1] + v[2] * wr[2] + v[3] * wr[3]
               + v[4] * wr[4] + v[5] * wr[5] + v[6] * wr[6] + v[7] * wr[7];
    }
#pragma unroll
    for (int off = 16; off; off >>= 1)
#pragma unroll
        for (int j = 0; j < 8; j++) acc[j] += __shfl_xor_sync(0xffffffffu, acc[j], off);
    if (lane == 0) {
        *(float4*)&g_as2[n * 4] = make_float4(acc[0], acc[1], acc[2], acc[3]);
        *(float4*)&g_ad2[n * 4] = make_float4(acc[4], acc[5], acc[6], acc[7]);
#pragma unroll
        for (int j = 0; j < 4; j++) atomicMax(&bmax[j], enc_f(acc[j]));
    }
    __syncthreads();
    if (threadIdx.x < 4) atomicMax(&g_gmax2[threadIdx.x], bmax[threadIdx.x]);
}

// ---------------- layer-2 aggregation over z (16 outputs per node) ----------------
// lane l owns z columns 2l,2l+1 (j = h*16+k: h = l>>3, k = (2l)&15).
__global__ void agg2_k(const float* __restrict__ z, const int* __restrict__ gmax,
                       float* __restrict__ out) {
    __shared__ float ps[8][32][4];
    int n = (blockIdx.x * 256 + threadIdx.x) >> 5;
    int lane = threadIdx.x & 31;
    int w = threadIdx.x >> 5;
    int beg = g_rowptr[n], end = g_rowptr[n + 1];
    float4 ad4 = *(const float4*)&g_ad2[n * 4];
    float m0 = dec_f(gmax[0]) + ad4.x; m0 = fmaxf(m0, 0.2f * m0);
    float m1 = dec_f(gmax[1]) + ad4.y; m1 = fmaxf(m1, 0.2f * m1);
    float m2 = dec_f(gmax[2]) + ad4.z; m2 = fmaxf(m2, 0.2f * m2);
    float m3 = dec_f(gmax[3]) + ad4.w; m3 = fmaxf(m3, 0.2f * m3);

    float a0 = 0.f, a1 = 0.f;
    float s0 = 0.f, s1 = 0.f, s2 = 0.f, s3 = 0.f;
    int hd = lane >> 3;
    const float* zp = z + 2 * lane;

    for (int base = beg; base < end; base += 32) {
        int i = base + lane;
        float p0 = 0.f, p1 = 0.f, p2 = 0.f, p3 = 0.f;
        int sj = 0;
        if (i < end) {
            sj = g_csr_src[i];
            float4 as4 = *(const float4*)&g_as2[sj * 4];
            float e;
            e = as4.x + ad4.x; e = fmaxf(e, 0.2f * e); p0 = __expf(e - m0);
            e = as4.y + ad4.y; e = fmaxf(e, 0.2f * e); p1 = __expf(e - m1);
            e = as4.z + ad4.z; e = fmaxf(e, 0.2f * e); p2 = __expf(e - m2);
            e = as4.w + ad4.w; e = fmaxf(e, 0.2f * e); p3 = __expf(e - m3);
        }
        s0 += p0; s1 += p1; s2 += p2; s3 += p3;
        ps[w][lane][0] = p0; ps[w][lane][1] = p1;
        ps[w][lane][2] = p2; ps[w][lane][3] = p3;
        __syncwarp();
        int cnt = min(32, end - base);
#pragma unroll 8
        for (int j = 0; j < cnt; j++) {
            int sc = __shfl_sync(0xffffffffu, sj, j);
            float p = ps[w][j][hd];
            float2 zv = *(const float2*)(zp + (size_t)sc * 64);
            a0 += p * zv.x;
            a1 += p * zv.y;
        }
        __syncwarp();
    }
#pragma unroll
    for (int off = 16; off; off >>= 1) {
        s0 += __shfl_xor_sync(0xffffffffu, s0, off);
        s1 += __shfl_xor_sync(0xffffffffu, s1, off);
        s2 += __shfl_xor_sync(0xffffffffu, s2, off);
        s3 += __shfl_xor_sync(0xffffffffu, s3, off);
    }
    float sv = (hd == 0) ? s0 : (hd == 1) ? s1 : (hd == 2) ? s2 : s3;
    float inv = 0.25f / sv;      // folds head-mean
    a0 *= inv; a1 *= inv;
    // sum over heads: lanes l, l+8, l+16, l+24 hold the same k = 2l mod 16
    a0 += __shfl_xor_sync(0xffffffffu, a0, 8);
    a1 += __shfl_xor_sync(0xffffffffu, a1, 8);
    a0 += __shfl_xor_sync(0xffffffffu, a0, 16);
    a1 += __shfl_xor_sync(0xffffffffu, a1, 16);
    if (lane < 8) {
        float2 cv = *(const float2*)&g_cvec[2 * lane];
        *(float2*)&out[n * 16 + 2 * lane] = make_float2(a0 + cv.x, a1 + cv.y);
    }
}

// ---------------- launch (single stream, 8 launches) ----------------
extern "C" void kernel_launch(void* const* d_in, const int* in_sizes, int n_in,
                              void* d_out, int out_size) {
    const float* x     = (const float*)d_in[0];
    const int*   ei    = (const int*)d_in[1];
    const float* W1    = (const float*)d_in[2];
    const float* atts1 = (const float*)d_in[3];
    const float* attd1 = (const float*)d_in[4];
    const float* b1    = (const float*)d_in[5];
    const float* W2    = (const float*)d_in[6];
    const float* atts2 = (const float*)d_in[7];
    const float* attd2 = (const float*)d_in[8];
    const float* b2    = (const float*)d_in[9];
    const float* Wout  = (const float*)d_in[10];
    const float* bout  = (const float*)d_in[11];
    float* out = (float*)d_out;

    __half* ghh;   cudaGetSymbolAddress((void**)&ghh, g_hh);
    __half* gxh;   cudaGetSymbolAddress((void**)&gxh, g_xh);
    __half* gx2h;  cudaGetSymbolAddress((void**)&gx2h, g_x2h);
    float*  gz;    cudaGetSymbolAddress((void**)&gz, g_z);
    __half* gbt1;  cudaGetSymbolAddress((void**)&gbt1, g_bt1);
    __half* gbtz;  cudaGetSymbolAddress((void**)&gbtz, g_btz);
    float* gwsd1;  cudaGetSymbolAddress((void**)&gwsd1, g_wsd1);
    float* gwsd2;  cudaGetSymbolAddress((void**)&gwsd2, g_wsd2);
    int* ggm1;     cudaGetSymbolAddress((void**)&ggm1, g_gmax1);
    int* ggm2;     cudaGetSymbolAddress((void**)&ggm2, g_gmax2);

    prep_k<<<204, 256>>>(W1, atts1, attd1, W2, atts2, attd2, Wout, b2, bout);
    asad1_k<<<NN / 8, 256>>>(x, gwsd1, ei);
    mma_gemm_k<128, 256, false><<<dim3(4, NNP / 128), 256>>>(gxh, gbt1, ghh, nullptr, NN);
    scan_k<<<SBLK, 256>>>();
    scatter_k<<<(QT + 255) / 256, 256>>>(ei);

    agg1_k<<<NN / 8, 256>>>(ghh, b1, ggm1, gwsd2);

    // z = x2 @ W2z   (N = 64, fp32 out)
    mma_gemm_k<256, 64, true><<<dim3(1, NNP / 128), 256>>>(gx2h, gbtz, nullptr, gz, NN);
    agg2_k<<<NN / 8, 256>>>(gz, ggm2, out);
}

// round 16
// speedup vs baseline: 1.2644x; 1.0392x over previous
#include <cuda_runtime.h>
#include <cuda_bf16.h>
#include <cuda_fp16.h>
#include <math.h>

#define NN 20000
#define NNP 20096
#define NE 640000
#define ET (NE + NN)
#define FH 4
#define CC 64
#define HC 256
#define SBLK 79   // ceil(NN/256)

// ---------------- device scratch ----------------
__device__ __half g_hh[NN * HC];     // layer-1 features fp16 (agg1 gather)
__device__ __half g_xh[NNP * 128];   // fp16 x (GEMM1 A); pad rows stay zero
__device__ __half g_x2h[NNP * HC];   // fp16 elu(agg1+b1) (GEMM-z A); pad rows zero
__device__ __half g_zh[NNP * 64];    // z = x2 @ W2z  (fp16, agg2 gather)
__device__ float  g_as[NN * FH];
__device__ float  g_ad[NN * FH];
__device__ float  g_as2[NN * FH];
__device__ float  g_ad2[NN * FH];
__device__ int    g_gmax1[FH];
__device__ int    g_gmax2[FH];
__device__ int    g_deg[NN];
__device__ int    g_bsum[SBLK];
__device__ int    g_flag[SBLK];
__device__ int    g_rowptr[NN + 1];
__device__ int    g_fill[NN];
__device__ int    g_csr_src[ET];
__device__ __half g_bt1[256 * 128];  // W1^T fp16
__device__ __half g_btz[64 * 256];   // (W2 @ blockdiag(Wout))^T fp16
__device__ float  g_wsd1[8 * 128];
__device__ float  g_wsd2[8 * 256];
__device__ float  g_cvec[16];        // b2 @ Wout + bout

__device__ __forceinline__ int enc_f(float f) {
    int i = __float_as_int(f);
    return i >= 0 ? i : (i ^ 0x7FFFFFFF);
}
__device__ __forceinline__ float dec_f(int u) {
    return __int_as_float(u >= 0 ? u : (u ^ 0x7FFFFFFF));
}

// ---------------- prep: bt1 + btz + wsd + cvec + deg/gmax/flag init, ONE launch ----------------
__global__ void prep_k(const float* __restrict__ W1, const float* __restrict__ atts1,
                       const float* __restrict__ attd1,
                       const float* __restrict__ W2, const float* __restrict__ atts2,
                       const float* __restrict__ attd2,
                       const float* __restrict__ Wout, const float* __restrict__ b2,
                       const float* __restrict__ bout) {
    if (blockIdx.x < 128) {
        int i = blockIdx.x * 256 + threadIdx.x;
        int r = i >> 8, c = i & 255;
        g_bt1[c * 128 + r] = __float2half(W1[i]);
        return;
    }
    if (blockIdx.x < 192) {
        int i = (blockIdx.x - 128) * 256 + threadIdx.x;   // 16384 outputs
        int r = i >> 6, j = i & 63;                 // r: K-row 0..255, j: out col 0..63
        int hd = j >> 4, k = j & 15;
        const float* w2r = W2 + r * 256 + hd * 64;
        const float* wo = Wout + k;
        float s = 0.f;
#pragma unroll 16
        for (int c = 0; c < 64; c++) s += w2r[c] * wo[c * 16];
        g_btz[j * 256 + r] = __float2half(s);
        return;
    }
    int t = (blockIdx.x - 192) * 256 + threadIdx.x;   // 0..3071
    if (t < 8) { g_gmax1[t] = (int)0x80000000; g_gmax2[t] = (int)0x80000000; }
    if (t == 8) g_rowptr[NN] = ET;
    if (t < 16) {
        float s = bout[t];
#pragma unroll 16
        for (int c = 0; c < 64; c++) s += b2[c] * Wout[c * 16 + t];
        g_cvec[t] = s;
    }
    for (int i = t; i < SBLK; i += 3072) g_flag[i] = 0;
    for (int i = t; i < NN; i += 3072) g_deg[i] = 1;  // self-loop pre-counted
    if (t < 1024) {
        int j = t >> 7, k = t & 127;
        int hd = j & 3;
        const float* av = (j < 4 ? atts1 : attd1) + hd * 64;
        const float* wr = W1 + k * 256 + hd * 64;
        float s = 0.f;
#pragma unroll 16
        for (int c = 0; c < 64; c++) s += wr[c] * av[c];
        g_wsd1[j * 128 + k] = s;
    } else {
        int t2 = t - 1024;
        int j = t2 >> 8, k = t2 & 255;
        int hd = j & 3;
        const float* av = (j < 4 ? atts2 : attd2) + hd * 64;
        const float* wr = W2 + k * 256 + hd * 64;
        float s = 0.f;
#pragma unroll 16
        for (int c = 0; c < 64; c++) s += wr[c] * av[c];
        g_wsd2[j * 256 + k] = s;
    }
}

// ---------------- single-pass scan with parallel aggregate lookback ----------------
__global__ void scan_k() {
    __shared__ int sm[256];
    __shared__ int soff;
    int t = threadIdx.x, b = blockIdx.x;
    int i = b * 256 + t;
    int d = (i < NN) ? g_deg[i] : 0;
    sm[t] = d;
    if (t == 0) soff = 0;
    __syncthreads();
    for (int off = 1; off < 256; off <<= 1) {
        int v = (t >= off) ? sm[t - off] : 0;
        __syncthreads();
        sm[t] += v;
        __syncthreads();
    }
    int incl = sm[t];
    if (t == 255) {
        g_bsum[b] = incl;
        __threadfence();
        atomicExch(&g_flag[b], 1);
    }
    if (t < b) {
        while (atomicAdd(&g_flag[t], 0) == 0) {}
        __threadfence();
        atomicAdd(&soff, g_bsum[t]);
    }
    __syncthreads();
    if (i < NN) {
        int r = soff + incl - d;
        g_rowptr[i] = r;
        g_csr_src[r] = i;            // self-loop in slot 0
        g_fill[i] = r + 1;
    }
}

#define QT ((NE + 3) / 4)
__global__ void scatter_k(const int* __restrict__ ei) {
    int t = blockIdx.x * blockDim.x + threadIdx.x;
    if (t >= QT) return;
#pragma unroll
    for (int r = 0; r < 4; r++) {
        int e = t + r * QT;
        if (e < NE) {
            int src = ei[e], dst = ei[NE + e];
            int p = atomicAdd(&g_fill[dst], 1);
            g_csr_src[p] = src;
        }
    }
}

// ---------------- as/ad layer 1 + fp16 convert + fused edge histogram ----------------
__global__ void asad1_k(const float* __restrict__ x, const float* __restrict__ wsdt,
                        const int* __restrict__ ei) {
    __shared__ int bmax[4];
    if (threadIdx.x < 4) bmax[threadIdx.x] = (int)0x80000000;
    int e = blockIdx.x * 256 + threadIdx.x;        // NE threads exactly
    int hd_dst = ei[NE + e];
    atomicAdd(&g_deg[hd_dst], 1);
    __syncthreads();
    int n = (blockIdx.x * 256 + threadIdx.x) >> 5;
    int lane = threadIdx.x & 31;
    float4 xv = *(const float4*)&x[n * 128 + lane * 4];
    {
        uint2 u;
        *(__half2*)&u.x = __floats2half2_rn(xv.x, xv.y);
        *(__half2*)&u.y = __floats2half2_rn(xv.z, xv.w);
        *(uint2*)&g_xh[n * 128 + lane * 4] = u;
    }
    float acc[8];
#pragma unroll
    for (int j = 0; j < 8; j++) {
        float4 w = *(const float4*)&wsdt[j * 128 + lane * 4];
        acc[j] = xv.x * w.x + xv.y * w.y + xv.z * w.z + xv.w * w.w;
    }
#pragma unroll
    for (int off = 16; off; off >>= 1)
#pragma unroll
        for (int j = 0; j < 8; j++) acc[j] += __shfl_xor_sync(0xffffffffu, acc[j], off);
    if (lane == 0) {
        *(float4*)&g_as[n * 4] = make_float4(acc[0], acc[1], acc[2], acc[3]);
        *(float4*)&g_ad[n * 4] = make_float4(acc[4], acc[5], acc[6], acc[7]);
#pragma unroll
        for (int j = 0; j < 4; j++) atomicMax(&bmax[j], enc_f(acc[j]));
    }
    __syncthreads();
    if (threadIdx.x < 4) atomicMax(&g_gmax1[threadIdx.x], bmax[threadIdx.x]);
}

// ---------------- 2-stage pipelined fp16 tensor-core GEMM ----------------
__device__ __forceinline__ void mma_f16(float* c, const unsigned* a, const unsigned* b) {
    asm volatile(
        "mma.sync.aligned.m16n8k16.row.col.f32.f16.f16.f32 "
        "{%0,%1,%2,%3}, {%4,%5,%6,%7}, {%8,%9}, {%0,%1,%2,%3};\n"
        : "+f"(c[0]), "+f"(c[1]), "+f"(c[2]), "+f"(c[3])
        : "r"(a[0]), "r"(a[1]), "r"(a[2]), "r"(a[3]), "r"(b[0]), "r"(b[1]));
}

template <int KP, int NOUT>
__global__ void mma_gemm_k(const __half* __restrict__ A,
                           const __half* __restrict__ BT,
                           __half* __restrict__ Ch, int M) {
    const int BM = 128, BN = 64, BK = 32, LD = 40;
    __shared__ __align__(16) __half As[2][BM * LD];
    __shared__ __align__(16) __half Bs[2][BN * LD];
    int t = threadIdx.x, lane = t & 31, wid = t >> 5;
    int wm = wid & 3, wn = wid >> 2;
    int bm = blockIdx.y * BM, bn = blockIdx.x * BN;
    float acc[2][4][4] = {};

    int ar = t >> 1, ac = (t & 1) * 16;
    int brow = t >> 2, bcol = (t & 3) * 8;

    auto load_tile = [&](int k0, int st) {
        const __half* ag = A + (size_t)(bm + ar) * KP + k0 + ac;
        unsigned sa = (unsigned)__cvta_generic_to_shared(&As[st][ar * LD + ac]);
        asm volatile("cp.async.ca.shared.global [%0], [%1], 16;\n" :: "r"(sa), "l"(ag) : "memory");
        asm volatile("cp.async.ca.shared.global [%0], [%1], 16;\n" :: "r"(sa + 16), "l"(ag + 8) : "memory");
        const __half* bg = BT + (size_t)(bn + brow) * KP + k0 + bcol;
        unsigned sb = (unsigned)__cvta_generic_to_shared(&Bs[st][brow * LD + bcol]);
        asm volatile("cp.async.ca.shared.global [%0], [%1], 16;\n" :: "r"(sb), "l"(bg) : "memory");
        asm volatile("cp.async.commit_group;\n" ::: "memory");
    };

    load_tile(0, 0);
    const int NT = KP / BK;
    for (int i = 0; i < NT; i++) {
        if (i + 1 < NT) {
            load_tile((i + 1) * BK, (i + 1) & 1);
            asm volatile("cp.async.wait_group 1;\n" ::: "memory");
        } else {
            asm volatile("cp.async.wait_group 0;\n" ::: "memory");
        }
        __syncthreads();
        int st = i & 1;
#pragma unroll
        for (int kk = 0; kk < BK; kk += 16) {
            unsigned af[2][4], bf[2][4];
#pragma unroll
            for (int mt = 0; mt < 2; mt++) {
                unsigned addr = (unsigned)__cvta_generic_to_shared(
                    &As[st][(wm * 32 + mt * 16 + (lane & 15)) * LD + kk + (lane >> 4) * 8]);
                asm volatile("ldmatrix.sync.aligned.m8n8.x4.shared.b16 {%0,%1,%2,%3}, [%4];\n"
                             : "=r"(af[mt][0]), "=r"(af[mt][1]), "=r"(af[mt][2]), "=r"(af[mt][3])
                             : "r"(addr));
            }
#pragma unroll
            for (int nb = 0; nb < 2; nb++) {
                int nr = wn * 32 + nb * 16 + (lane & 7) + ((lane >> 4) << 3);
                int kc = kk + ((lane >> 3) & 1) * 8;
                unsigned addr = (unsigned)__cvta_generic_to_shared(&Bs[st][nr * LD + kc]);
                asm volatile("ldmatrix.sync.aligned.m8n8.x4.shared.b16 {%0,%1,%2,%3}, [%4];\n"
                             : "=r"(bf[nb][0]), "=r"(bf[nb][1]), "=r"(bf[nb][2]), "=r"(bf[nb][3])
                             : "r"(addr));
            }
#pragma unroll
            for (int mt = 0; mt < 2; mt++)
#pragma unroll
                for (int nt = 0; nt < 4; nt++) {
                    unsigned bq[2] = { bf[nt >> 1][(nt & 1) * 2], bf[nt >> 1][(nt & 1) * 2 + 1] };
                    mma_f16(acc[mt][nt], af[mt], bq);
                }
        }
        __syncthreads();
    }

    int g = lane >> 2, tg = lane & 3;
#pragma unroll
    for (int mt = 0; mt < 2; mt++) {
        int r0 = bm + wm * 32 + mt * 16 + g;
#pragma unroll
        for (int nt = 0; nt < 4; nt++) {
            int c = bn + wn * 32 + nt * 8 + tg * 2;
            if (r0 < M)
                *(__half2*)&Ch[(size_t)r0 * NOUT + c] = __floats2half2_rn(acc[mt][nt][0], acc[mt][nt][1]);
            if (r0 + 8 < M)
                *(__half2*)&Ch[(size_t)(r0 + 8) * NOUT + c] = __floats2half2_rn(acc[mt][nt][2], acc[mt][nt][3]);
        }
    }
}

// ---------------- layer-1 aggregation + fused layer-2 logits ----------------
__global__ void agg1_k(const __half* __restrict__ hh, const float* __restrict__ bias,
                       const int* __restrict__ gmax, const float* __restrict__ wsd2) {
    __shared__ float ps[8][32][4];
    __shared__ float w2s[8 * 256];
    __shared__ int bmax[4];
    {
        int t = threadIdx.x;
        for (int i = t; i < 8 * 256; i += 256) w2s[i] = wsd2[i];
        if (t < 4) bmax[t] = (int)0x80000000;
        __syncthreads();
    }
    int n = (blockIdx.x * 256 + threadIdx.x) >> 5;
    int lane = threadIdx.x & 31;
    int w = threadIdx.x >> 5;
    int beg = g_rowptr[n], end = g_rowptr[n + 1];
    float4 ad4 = *(const float4*)&g_ad[n * 4];
    float m0 = dec_f(gmax[0]) + ad4.x; m0 = fmaxf(m0, 0.2f * m0);
    float m1 = dec_f(gmax[1]) + ad4.y; m1 = fmaxf(m1, 0.2f * m1);
    float m2 = dec_f(gmax[2]) + ad4.z; m2 = fmaxf(m2, 0.2f * m2);
    float m3 = dec_f(gmax[3]) + ad4.w; m3 = fmaxf(m3, 0.2f * m3);

    float a[8] = {};
    float s0 = 0.f, s1 = 0.f, s2 = 0.f, s3 = 0.f;
    int hd = lane >> 3;
    const __half* hp = hh + lane * 8;

    for (int base = beg; base < end; base += 32) {
        int i = base + lane;
        float p0 = 0.f, p1 = 0.f, p2 = 0.f, p3 = 0.f;
        int sj = 0;
        if (i < end) {
            sj = g_csr_src[i];
            float4 as4 = *(const float4*)&g_as[sj * 4];
            float e;
            e = as4.x + ad4.x; e = fmaxf(e, 0.2f * e); p0 = __expf(e - m0);
            e = as4.y + ad4.y; e = fmaxf(e, 0.2f * e); p1 = __expf(e - m1);
            e = as4.z + ad4.z; e = fmaxf(e, 0.2f * e); p2 = __expf(e - m2);
            e = as4.w + ad4.w; e = fmaxf(e, 0.2f * e); p3 = __expf(e - m3);
        }
        s0 += p0; s1 += p1; s2 += p2; s3 += p3;
        ps[w][lane][0] = p0; ps[w][lane][1] = p1;
        ps[w][lane][2] = p2; ps[w][lane][3] = p3;
        __syncwarp();
        int cnt = min(32, end - base);
#pragma unroll 8
        for (int j = 0; j < cnt; j++) {
            int sc = __shfl_sync(0xffffffffu, sj, j);
            float p = ps[w][j][hd];
            uint4 v = *(const uint4*)(hp + sc * HC);
            __half2* hv = (__half2*)&v;
            float2 f0 = __half22float2(hv[0]);
            float2 f1 = __half22float2(hv[1]);
            float2 f2 = __half22float2(hv[2]);
            float2 f3 = __half22float2(hv[3]);
            a[0] += p * f0.x; a[1] += p * f0.y;
            a[2] += p * f1.x; a[3] += p * f1.y;
            a[4] += p * f2.x; a[5] += p * f2.y;
            a[6] += p * f3.x; a[7] += p * f3.y;
        }
        __syncwarp();
    }
#pragma unroll
    for (int off = 16; off; off >>= 1) {
        s0 += __shfl_xor_sync(0xffffffffu, s0, off);
        s1 += __shfl_xor_sync(0xffffffffu, s1, off);
        s2 += __shfl_xor_sync(0xffffffffu, s2, off);
        s3 += __shfl_xor_sync(0xffffffffu, s3, off);
    }
    float sv = (hd == 0) ? s0 : (hd == 1) ? s1 : (hd == 2) ? s2 : s3;
    float inv = 1.f / sv;
    int ch = lane * 8;
    float4 bA = *(const float4*)&bias[ch];
    float4 bB = *(const float4*)&bias[ch + 4];
    float v[8];
    v[0] = a[0] * inv + bA.x; v[1] = a[1] * inv + bA.y;
    v[2] = a[2] * inv + bA.z; v[3] = a[3] * inv + bA.w;
    v[4] = a[4] * inv + bB.x; v[5] = a[5] * inv + bB.y;
    v[6] = a[6] * inv + bB.z; v[7] = a[7] * inv + bB.w;
#pragma unroll
    for (int t = 0; t < 8; t++) v[t] = (v[t] > 0.f) ? v[t] : (__expf(v[t]) - 1.f);
    {
        uint4 o;
        __half2* oh = (__half2*)&o;
        oh[0] = __floats2half2_rn(v[0], v[1]);
        oh[1] = __floats2half2_rn(v[2], v[3]);
        oh[2] = __floats2half2_rn(v[4], v[5]);
        oh[3] = __floats2half2_rn(v[6], v[7]);
        *(uint4*)&g_x2h[n * 256 + ch] = o;
    }
    float acc[8];
#pragma unroll
    for (int j = 0; j < 8; j++) {
        const float* wr = &w2s[j * 256 + ch];
        acc[j] = v[0] * wr[0] + v[1] * wr[1] + v[2] * wr[2] + v[3] * wr[3]
               + v[4] * wr[4] + v[5] * wr[5] + v[6] * wr[6] + v[7] * wr[7];
    }
#pragma unroll
    for (int off = 16; off; off >>= 1)
#pragma unroll
        for (int j = 0; j < 8; j++) acc[j] += __shfl_xor_sync(0xffffffffu, acc[j], off);
    if (lane == 0) {
        *(float4*)&g_as2[n * 4] = make_float4(acc[0], acc[1], acc[2], acc[3]);
        *(float4*)&g_ad2[n * 4] = make_float4(acc[4], acc[5], acc[6], acc[7]);
#pragma unroll
        for (int j = 0; j < 4; j++) atomicMax(&bmax[j], enc_f(acc[j]));
    }
    __syncthreads();
    if (threadIdx.x < 4) atomicMax(&g_gmax2[threadIdx.x], bmax[threadIdx.x]);
}

// ---------------- layer-2 aggregation over fp16 z (16 outputs per node) ----------------
__global__ void agg2_k(const __half* __restrict__ z, const int* __restrict__ gmax,
                       float* __restrict__ out) {
    __shared__ float ps[8][32][4];
    int n = (blockIdx.x * 256 + threadIdx.x) >> 5;
    int lane = threadIdx.x & 31;
    int w = threadIdx.x >> 5;
    int beg = g_rowptr[n], end = g_rowptr[n + 1];
    float4 ad4 = *(const float4*)&g_ad2[n * 4];
    float m0 = dec_f(gmax[0]) + ad4.x; m0 = fmaxf(m0, 0.2f * m0);
    float m1 = dec_f(gmax[1]) + ad4.y; m1 = fmaxf(m1, 0.2f * m1);
    float m2 = dec_f(gmax[2]) + ad4.z; m2 = fmaxf(m2, 0.2f * m2);
    float m3 = dec_f(gmax[3]) + ad4.w; m3 = fmaxf(m3, 0.2f * m3);

    float a0 = 0.f, a1 = 0.f;
    float s0 = 0.f, s1 = 0.f, s2 = 0.f, s3 = 0.f;
    int hd = lane >> 3;
    const __half* zp = z + 2 * lane;

    for (int base = beg; base < end; base += 32) {
        int i = base + lane;
        float p0 = 0.f, p1 = 0.f, p2 = 0.f, p3 = 0.f;
        int sj = 0;
        if (i < end) {
            sj = g_csr_src[i];
            float4 as4 = *(const float4*)&g_as2[sj * 4];
            float e;
            e = as4.x + ad4.x; e = fmaxf(e, 0.2f * e); p0 = __expf(e - m0);
            e = as4.y + ad4.y; e = fmaxf(e, 0.2f * e); p1 = __expf(e - m1);
            e = as4.z + ad4.z; e = fmaxf(e, 0.2f * e); p2 = __expf(e - m2);
            e = as4.w + ad4.w; e = fmaxf(e, 0.2f * e); p3 = __expf(e - m3);
        }
        s0 += p0; s1 += p1; s2 += p2; s3 += p3;
        ps[w][lane][0] = p0; ps[w][lane][1] = p1;
        ps[w][lane][2] = p2; ps[w][lane][3] = p3;
        __syncwarp();
        int cnt = min(32, end - base);
#pragma unroll 8
        for (int j = 0; j < cnt; j++) {
            int sc = __shfl_sync(0xffffffffu, sj, j);
            float p = ps[w][j][hd];
            float2 zv = __half22float2(*(const __half2*)(zp + (size_t)sc * 64));
            a0 += p * zv.x;
            a1 += p * zv.y;
        }
        __syncwarp();
    }
#pragma unroll
    for (int off = 16; off; off >>= 1) {
        s0 += __shfl_xor_sync(0xffffffffu, s0, off);
        s1 += __shfl_xor_sync(0xffffffffu, s1, off);
        s2 += __shfl_xor_sync(0xffffffffu, s2, off);
        s3 += __shfl_xor_sync(0xffffffffu, s3, off);
    }
    float sv = (hd == 0) ? s0 : (hd == 1) ? s1 : (hd == 2) ? s2 : s3;
    float inv = 0.25f / sv;      // folds head-mean
    a0 *= inv; a1 *= inv;
    a0 += __shfl_xor_sync(0xffffffffu, a0, 8);
    a1 += __shfl_xor_sync(0xffffffffu, a1, 8);
    a0 += __shfl_xor_sync(0xffffffffu, a0, 16);
    a1 += __shfl_xor_sync(0xffffffffu, a1, 16);
    if (lane < 8) {
        float2 cv = *(const float2*)&g_cvec[2 * lane];
        *(float2*)&out[n * 16 + 2 * lane] = make_float2(a0 + cv.x, a1 + cv.y);
    }
}

// ---------------- launch (single stream, 8 launches) ----------------
extern "C" void kernel_launch(void* const* d_in, const int* in_sizes, int n_in,
                              void* d_out, int out_size) {
    const float* x     = (const float*)d_in[0];
    const int*   ei    = (const int*)d_in[1];
    const float* W1    = (const float*)d_in[2];
    const float* atts1 = (const float*)d_in[3];
    const float* attd1 = (const float*)d_in[4];
    const float* b1    = (const float*)d_in[5];
    const float* W2    = (const float*)d_in[6];
    const float* atts2 = (const float*)d_in[7];
    const float* attd2 = (const float*)d_in[8];
    const float* b2    = (const float*)d_in[9];
    const float* Wout  = (const float*)d_in[10];
    const float* bout  = (const float*)d_in[11];
    float* out = (float*)d_out;

    __half* ghh;   cudaGetSymbolAddress((void**)&ghh, g_hh);
    __half* gxh;   cudaGetSymbolAddress((void**)&gxh, g_xh);
    __half* gx2h;  cudaGetSymbolAddress((void**)&gx2h, g_x2h);
    __half* gzh;   cudaGetSymbolAddress((void**)&gzh, g_zh);
    __half* gbt1;  cudaGetSymbolAddress((void**)&gbt1, g_bt1);
    __half* gbtz;  cudaGetSymbolAddress((void**)&gbtz, g_btz);
    float* gwsd1;  cudaGetSymbolAddress((void**)&gwsd1, g_wsd1);
    float* gwsd2;  cudaGetSymbolAddress((void**)&gwsd2, g_wsd2);
    int* ggm1;     cudaGetSymbolAddress((void**)&ggm1, g_gmax1);
    int* ggm2;     cudaGetSymbolAddress((void**)&ggm2, g_gmax2);

    prep_k<<<204, 256>>>(W1, atts1, attd1, W2, atts2, attd2, Wout, b2, bout);
    asad1_k<<<NN / 8, 256>>>(x, gwsd1, ei);
    mma_gemm_k<128, 256><<<dim3(4, NNP / 128), 256>>>(gxh, gbt1, ghh, NN);
    scan_k<<<SBLK, 256>>>();
    scatter_k<<<(QT + 255) / 256, 256>>>(ei);

    agg1_k<<<NN / 8, 256>>>(ghh, b1, ggm1, gwsd2);

    // z = x2 @ W2z   (N = 64, fp16 out)
    mma_gemm_k<256, 64><<<dim3(1, NNP / 128), 256>>>(gx2h, gbtz, gzh, NN);
    agg2_k<<<NN / 8, 256>>>(gzh, ggm2, out);
}

// round 17
// speedup vs baseline: 1.2905x; 1.0206x over previous
#include <cuda_runtime.h>
#include <cuda_bf16.h>
#include <cuda_fp16.h>
#include <math.h>

#define NN 20000
#define NNP 20096
#define NE 640000
#define ET (NE + NN)
#define FH 4
#define CC 64
#define HC 256
#define SBLK 79   // ceil(NN/256)
#define QT ((NE + 3) / 4)          // 160000 -> 625 blocks exactly
#define GEMM1_BLKS (4 * (NNP / 128))   // 628
#define MID_BLKS (SBLK + GEMM1_BLKS + QT / 256)   // 79 + 628 + 625 = 1332

// ---------------- device scratch ----------------
__device__ __half g_hh[NN * HC];     // layer-1 features fp16 (agg1 gather)
__device__ __half g_xh[NNP * 128];   // fp16 x (GEMM1 A); pad rows stay zero
__device__ __half g_x2h[NNP * HC];   // fp16 elu(agg1+b1) (GEMM-z A); pad rows zero
__device__ __half g_zh[NNP * 64];    // z = x2 @ W2z  (fp16, agg2 gather)
__device__ float  g_as[NN * FH];
__device__ float  g_ad[NN * FH];
__device__ float  g_as2[NN * FH];
__device__ float  g_ad2[NN * FH];
__device__ int    g_gmax1[FH];
__device__ int    g_gmax2[FH];
__device__ int    g_deg[NN];
__device__ int    g_bsum[SBLK];
__device__ int    g_flag[SBLK];
__device__ int    g_done;            // count of finished scan blocks
__device__ int    g_rowptr[NN + 1];
__device__ int    g_fill[NN];
__device__ int    g_csr_src[ET];
__device__ __half g_bt1[256 * 128];  // W1^T fp16
__device__ __half g_btz[64 * 256];   // (W2 @ blockdiag(Wout))^T fp16
__device__ float  g_wsd1[8 * 128];
__device__ float  g_wsd2[8 * 256];
__device__ float  g_cvec[16];        // b2 @ Wout + bout

__device__ __forceinline__ int enc_f(float f) {
    int i = __float_as_int(f);
    return i >= 0 ? i : (i ^ 0x7FFFFFFF);
}
__device__ __forceinline__ float dec_f(int u) {
    return __int_as_float(u >= 0 ? u : (u ^ 0x7FFFFFFF));
}

// ---------------- prep: bt1 + btz + wsd + cvec + init, ONE launch ----------------
__global__ void prep_k(const float* __restrict__ W1, const float* __restrict__ atts1,
                       const float* __restrict__ attd1,
                       const float* __restrict__ W2, const float* __restrict__ atts2,
                       const float* __restrict__ attd2,
                       const float* __restrict__ Wout, const float* __restrict__ b2,
                       const float* __restrict__ bout) {
    if (blockIdx.x < 128) {
        int i = blockIdx.x * 256 + threadIdx.x;
        int r = i >> 8, c = i & 255;
        g_bt1[c * 128 + r] = __float2half(W1[i]);
        return;
    }
    if (blockIdx.x < 192) {
        int i = (blockIdx.x - 128) * 256 + threadIdx.x;   // 16384 outputs
        int r = i >> 6, j = i & 63;
        int hd = j >> 4, k = j & 15;
        const float* w2r = W2 + r * 256 + hd * 64;
        const float* wo = Wout + k;
        float s = 0.f;
#pragma unroll 16
        for (int c = 0; c < 64; c++) s += w2r[c] * wo[c * 16];
        g_btz[j * 256 + r] = __float2half(s);
        return;
    }
    int t = (blockIdx.x - 192) * 256 + threadIdx.x;   // 0..3071
    if (t < 8) { g_gmax1[t] = (int)0x80000000; g_gmax2[t] = (int)0x80000000; }
    if (t == 8) g_rowptr[NN] = ET;
    if (t == 9) g_done = 0;
    if (t < 16) {
        float s = bout[t];
#pragma unroll 16
        for (int c = 0; c < 64; c++) s += b2[c] * Wout[c * 16 + t];
        g_cvec[t] = s;
    }
    for (int i = t; i < SBLK; i += 3072) g_flag[i] = 0;
    for (int i = t; i < NN; i += 3072) g_deg[i] = 1;  // self-loop pre-counted
    if (t < 1024) {
        int j = t >> 7, k = t & 127;
        int hd = j & 3;
        const float* av = (j < 4 ? atts1 : attd1) + hd * 64;
        const float* wr = W1 + k * 256 + hd * 64;
        float s = 0.f;
#pragma unroll 16
        for (int c = 0; c < 64; c++) s += wr[c] * av[c];
        g_wsd1[j * 128 + k] = s;
    } else {
        int t2 = t - 1024;
        int j = t2 >> 8, k = t2 & 255;
        int hd = j & 3;
        const float* av = (j < 4 ? atts2 : attd2) + hd * 64;
        const float* wr = W2 + k * 256 + hd * 64;
        float s = 0.f;
#pragma unroll 16
        for (int c = 0; c < 64; c++) s += wr[c] * av[c];
        g_wsd2[j * 256 + k] = s;
    }
}

// ---------------- as/ad layer 1 + fp16 convert + fused edge histogram ----------------
__global__ void asad1_k(const float* __restrict__ x, const float* __restrict__ wsdt,
                        const int* __restrict__ ei) {
    __shared__ int bmax[4];
    if (threadIdx.x < 4) bmax[threadIdx.x] = (int)0x80000000;
    int e = blockIdx.x * 256 + threadIdx.x;        // NE threads exactly
    int hd_dst = ei[NE + e];
    atomicAdd(&g_deg[hd_dst], 1);
    __syncthreads();
    int n = (blockIdx.x * 256 + threadIdx.x) >> 5;
    int lane = threadIdx.x & 31;
    float4 xv = *(const float4*)&x[n * 128 + lane * 4];
    {
        uint2 u;
        *(__half2*)&u.x = __floats2half2_rn(xv.x, xv.y);
        *(__half2*)&u.y = __floats2half2_rn(xv.z, xv.w);
        *(uint2*)&g_xh[n * 128 + lane * 4] = u;
    }
    float acc[8];
#pragma unroll
    for (int j = 0; j < 8; j++) {
        float4 w = *(const float4*)&wsdt[j * 128 + lane * 4];
        acc[j] = xv.x * w.x + xv.y * w.y + xv.z * w.z + xv.w * w.w;
    }
#pragma unroll
    for (int off = 16; off; off >>= 1)
#pragma unroll
        for (int j = 0; j < 8; j++) acc[j] += __shfl_xor_sync(0xffffffffu, acc[j], off);
    if (lane == 0) {
        *(float4*)&g_as[n * 4] = make_float4(acc[0], acc[1], acc[2], acc[3]);
        *(float4*)&g_ad[n * 4] = make_float4(acc[4], acc[5], acc[6], acc[7]);
#pragma unroll
        for (int j = 0; j < 4; j++) atomicMax(&bmax[j], enc_f(acc[j]));
    }
    __syncthreads();
    if (threadIdx.x < 4) atomicMax(&g_gmax1[threadIdx.x], bmax[threadIdx.x]);
}

// ---------------- fused mid kernel: scan (blocks 0..78) + GEMM1 (79..706) + scatter (707..1331) ----------------
__device__ __forceinline__ void mma_f16(float* c, const unsigned* a, const unsigned* b) {
    asm volatile(
        "mma.sync.aligned.m16n8k16.row.col.f32.f16.f16.f32 "
        "{%0,%1,%2,%3}, {%4,%5,%6,%7}, {%8,%9}, {%0,%1,%2,%3};\n"
        : "+f"(c[0]), "+f"(c[1]), "+f"(c[2]), "+f"(c[3])
        : "r"(a[0]), "r"(a[1]), "r"(a[2]), "r"(a[3]), "r"(b[0]), "r"(b[1]));
}

// generic gemm body (used by mid_k for gemm1 and standalone for gemm-z)
template <int KP, int NOUT>
__device__ __forceinline__ void gemm_body(const __half* __restrict__ A,
                                          const __half* __restrict__ BT,
                                          __half* __restrict__ Ch, int M,
                                          int bm, int bn, char* smem_raw) {
    const int BM = 128, BN = 64, BK = 32, LD = 40;
    __half (*As)[BM * LD] = (__half(*)[BM * LD])smem_raw;
    __half (*Bs)[BN * LD] = (__half(*)[BN * LD])(smem_raw + 2 * BM * LD * 2);
    int t = threadIdx.x, lane = t & 31, wid = t >> 5;
    int wm = wid & 3, wn = wid >> 2;
    float acc[2][4][4] = {};

    int ar = t >> 1, ac = (t & 1) * 16;
    int brow = t >> 2, bcol = (t & 3) * 8;

    auto load_tile = [&](int k0, int st) {
        const __half* ag = A + (size_t)(bm + ar) * KP + k0 + ac;
        unsigned sa = (unsigned)__cvta_generic_to_shared(&As[st][ar * LD + ac]);
        asm volatile("cp.async.ca.shared.global [%0], [%1], 16;\n" :: "r"(sa), "l"(ag) : "memory");
        asm volatile("cp.async.ca.shared.global [%0], [%1], 16;\n" :: "r"(sa + 16), "l"(ag + 8) : "memory");
        const __half* bg = BT + (size_t)(bn + brow) * KP + k0 + bcol;
        unsigned sb = (unsigned)__cvta_generic_to_shared(&Bs[st][brow * LD + bcol]);
        asm volatile("cp.async.ca.shared.global [%0], [%1], 16;\n" :: "r"(sb), "l"(bg) : "memory");
        asm volatile("cp.async.commit_group;\n" ::: "memory");
    };

    load_tile(0, 0);
    const int NT = KP / BK;
    for (int i = 0; i < NT; i++) {
        if (i + 1 < NT) {
            load_tile((i + 1) * BK, (i + 1) & 1);
            asm volatile("cp.async.wait_group 1;\n" ::: "memory");
        } else {
            asm volatile("cp.async.wait_group 0;\n" ::: "memory");
        }
        __syncthreads();
        int st = i & 1;
#pragma unroll
        for (int kk = 0; kk < BK; kk += 16) {
            unsigned af[2][4], bf[2][4];
#pragma unroll
            for (int mt = 0; mt < 2; mt++) {
                unsigned addr = (unsigned)__cvta_generic_to_shared(
                    &As[st][(wm * 32 + mt * 16 + (lane & 15)) * LD + kk + (lane >> 4) * 8]);
                asm volatile("ldmatrix.sync.aligned.m8n8.x4.shared.b16 {%0,%1,%2,%3}, [%4];\n"
                             : "=r"(af[mt][0]), "=r"(af[mt][1]), "=r"(af[mt][2]), "=r"(af[mt][3])
                             : "r"(addr));
            }
#pragma unroll
            for (int nb = 0; nb < 2; nb++) {
                int nr = wn * 32 + nb * 16 + (lane & 7) + ((lane >> 4) << 3);
                int kc = kk + ((lane >> 3) & 1) * 8;
                unsigned addr = (unsigned)__cvta_generic_to_shared(&Bs[st][nr * LD + kc]);
                asm volatile("ldmatrix.sync.aligned.m8n8.x4.shared.b16 {%0,%1,%2,%3}, [%4];\n"
                             : "=r"(bf[nb][0]), "=r"(bf[nb][1]), "=r"(bf[nb][2]), "=r"(bf[nb][3])
                             : "r"(addr));
            }
#pragma unroll
            for (int mt = 0; mt < 2; mt++)
#pragma unroll
                for (int nt = 0; nt < 4; nt++) {
                    unsigned bq[2] = { bf[nt >> 1][(nt & 1) * 2], bf[nt >> 1][(nt & 1) * 2 + 1] };
                    mma_f16(acc[mt][nt], af[mt], bq);
                }
        }
        __syncthreads();
    }

    int g = lane >> 2, tg = lane & 3;
#pragma unroll
    for (int mt = 0; mt < 2; mt++) {
        int r0 = bm + wm * 32 + mt * 16 + g;
#pragma unroll
        for (int nt = 0; nt < 4; nt++) {
            int c = bn + wn * 32 + nt * 8 + tg * 2;
            if (r0 < M)
                *(__half2*)&Ch[(size_t)r0 * NOUT + c] = __floats2half2_rn(acc[mt][nt][0], acc[mt][nt][1]);
            if (r0 + 8 < M)
                *(__half2*)&Ch[(size_t)(r0 + 8) * NOUT + c] = __floats2half2_rn(acc[mt][nt][2], acc[mt][nt][3]);
        }
    }
}

__global__ void __launch_bounds__(256) mid_k(const __half* __restrict__ A,
                                             const __half* __restrict__ BT,
                                             __half* __restrict__ Ch,
                                             const int* __restrict__ ei) {
    __shared__ __align__(16) char smem_raw[(2 * 128 * 40 + 2 * 64 * 40) * 2];
    int b = blockIdx.x;
    if (b < SBLK) {
        // ---- scan with parallel lookback ----
        int* sm = (int*)smem_raw;
        int* soff = sm + 256;
        int t = threadIdx.x;
        int i = b * 256 + t;
        int d = (i < NN) ? g_deg[i] : 0;
        sm[t] = d;
        if (t == 0) *soff = 0;
        __syncthreads();
        for (int off = 1; off < 256; off <<= 1) {
            int v = (t >= off) ? sm[t - off] : 0;
            __syncthreads();
            sm[t] += v;
            __syncthreads();
        }
        int incl = sm[t];
        if (t == 255) {
            g_bsum[b] = incl;
            __threadfence();
            atomicExch(&g_flag[b], 1);
        }
        if (t < b) {
            while (atomicAdd(&g_flag[t], 0) == 0) {}
            __threadfence();
            atomicAdd(soff, g_bsum[t]);
        }
        __syncthreads();
        if (i < NN) {
            int r = *soff + incl - d;
            g_rowptr[i] = r;
            g_csr_src[r] = i;        // self-loop in slot 0
            g_fill[i] = r + 1;
        }
        __syncthreads();
        if (t == 0) {
            __threadfence();
            atomicAdd(&g_done, 1);
        }
    } else if (b < SBLK + GEMM1_BLKS) {
        int idx = b - SBLK;
        int bn = (idx & 3) * 64;
        int bm = (idx >> 2) * 128;
        gemm_body<128, 256>(A, BT, Ch, NN, bm, bn, smem_raw);
    } else {
        // ---- scatter (spin until scan complete) ----
        if (threadIdx.x == 0) {
            while (atomicAdd(&g_done, 0) != SBLK) {}
        }
        __syncthreads();
        __threadfence();
        int t = (b - SBLK - GEMM1_BLKS) * 256 + threadIdx.x;
#pragma unroll
        for (int r = 0; r < 4; r++) {
            int e = t + r * QT;
            if (e < NE) {
                int src = ei[e], dst = ei[NE + e];
                int p = atomicAdd(&g_fill[dst], 1);
                g_csr_src[p] = src;
            }
        }
    }
}

// standalone gemm-z (N=64)
__global__ void __launch_bounds__(256) gemmz_k(const __half* __restrict__ A,
                                               const __half* __restrict__ BT,
                                               __half* __restrict__ Ch) {
    __shared__ __align__(16) char smem_raw[(2 * 128 * 40 + 2 * 64 * 40) * 2];
    gemm_body<256, 64>(A, BT, Ch, NN, blockIdx.x * 128, 0, smem_raw);
}

// ---------------- layer-1 aggregation + fused layer-2 logits ----------------
__global__ void agg1_k(const __half* __restrict__ hh, const float* __restrict__ bias,
                       const int* __restrict__ gmax, const float* __restrict__ wsd2) {
    __shared__ float ps[8][32][4];
    __shared__ float w2s[8 * 256];
    __shared__ int bmax[4];
    {
        int t = threadIdx.x;
        for (int i = t; i < 8 * 256; i += 256) w2s[i] = wsd2[i];
        if (t < 4) bmax[t] = (int)0x80000000;
        __syncthreads();
    }
    int n = (blockIdx.x * 256 + threadIdx.x) >> 5;
    int lane = threadIdx.x & 31;
    int w = threadIdx.x >> 5;
    int beg = g_rowptr[n], end = g_rowptr[n + 1];
    float4 ad4 = *(const float4*)&g_ad[n * 4];
    float m0 = dec_f(gmax[0]) + ad4.x; m0 = fmaxf(m0, 0.2f * m0);
    float m1 = dec_f(gmax[1]) + ad4.y; m1 = fmaxf(m1, 0.2f * m1);
    float m2 = dec_f(gmax[2]) + ad4.z; m2 = fmaxf(m2, 0.2f * m2);
    float m3 = dec_f(gmax[3]) + ad4.w; m3 = fmaxf(m3, 0.2f * m3);

    float a[8] = {};
    float s0 = 0.f, s1 = 0.f, s2 = 0.f, s3 = 0.f;
    int hd = lane >> 3;
    const __half* hp = hh + lane * 8;

    for (int base = beg; base < end; base += 32) {
        int i = base + lane;
        float p0 = 0.f, p1 = 0.f, p2 = 0.f, p3 = 0.f;
        int sj = 0;
        if (i < end) {
            sj = g_csr_src[i];
            float4 as4 = *(const float4*)&g_as[sj * 4];
            float e;
            e = as4.x + ad4.x; e = fmaxf(e, 0.2f * e); p0 = __expf(e - m0);
            e = as4.y + ad4.y; e = fmaxf(e, 0.2f * e); p1 = __expf(e - m1);
            e = as4.z + ad4.z; e = fmaxf(e, 0.2f * e); p2 = __expf(e - m2);
            e = as4.w + ad4.w; e = fmaxf(e, 0.2f * e); p3 = __expf(e - m3);
        }
        s0 += p0; s1 += p1; s2 += p2; s3 += p3;
        ps[w][lane][0] = p0; ps[w][lane][1] = p1;
        ps[w][lane][2] = p2; ps[w][lane][3] = p3;
        __syncwarp();
        int cnt = min(32, end - base);
#pragma unroll 8
        for (int j = 0; j < cnt; j++) {
            int sc = __shfl_sync(0xffffffffu, sj, j);
            float p = ps[w][j][hd];
            uint4 v = *(const uint4*)(hp + sc * HC);
            __half2* hv = (__half2*)&v;
            float2 f0 = __half22float2(hv[0]);
            float2 f1 = __half22float2(hv[1]);
            float2 f2 = __half22float2(hv[2]);
            float2 f3 = __half22float2(hv[3]);
            a[0] += p * f0.x; a[1] += p * f0.y;
            a[2] += p * f1.x; a[3] += p * f1.y;
            a[4] += p * f2.x; a[5] += p * f2.y;
            a[6] += p * f3.x; a[7] += p * f3.y;
        }
        __syncwarp();
    }
#pragma unroll
    for (int off = 16; off; off >>= 1) {
        s0 += __shfl_xor_sync(0xffffffffu, s0, off);
        s1 += __shfl_xor_sync(0xffffffffu, s1, off);
        s2 += __shfl_xor_sync(0xffffffffu, s2, off);
        s3 += __shfl_xor_sync(0xffffffffu, s3, off);
    }
    float sv = (hd == 0) ? s0 : (hd == 1) ? s1 : (hd == 2) ? s2 : s3;
    float inv = 1.f / sv;
    int ch = lane * 8;
    float4 bA = *(const float4*)&bias[ch];
    float4 bB = *(const float4*)&bias[ch + 4];
    float v[8];
    v[0] = a[0] * inv + bA.x; v[1] = a[1] * inv + bA.y;
    v[2] = a[2] * inv + bA.z; v[3] = a[3] * inv + bA.w;
    v[4] = a[4] * inv + bB.x; v[5] = a[5] * inv + bB.y;
    v[6] = a[6] * inv + bB.z; v[7] = a[7] * inv + bB.w;
#pragma unroll
    for (int t = 0; t < 8; t++) v[t] = (v[t] > 0.f) ? v[t] : (__expf(v[t]) - 1.f);
    {
        uint4 o;
        __half2* oh = (__half2*)&o;
        oh[0] = __floats2half2_rn(v[0], v[1]);
        oh[1] = __floats2half2_rn(v[2], v[3]);
        oh[2] = __floats2half2_rn(v[4], v[5]);
        oh[3] = __floats2half2_rn(v[6], v[7]);
        *(uint4*)&g_x2h[n * 256 + ch] = o;
    }
    float acc[8];
#pragma unroll
    for (int j = 0; j < 8; j++) {
        const float* wr = &w2s[j * 256 + ch];
        acc[j] = v[0] * wr[0] + v[1] * wr[1] + v[2] * wr[2] + v[3] * wr[3]
               + v[4] * wr[4] + v[5] * wr[5] + v[6] * wr[6] + v[7] * wr[7];
    }
#pragma unroll
    for (int off = 16; off; off >>= 1)
#pragma unroll
        for (int j = 0; j < 8; j++) acc[j] += __shfl_xor_sync(0xffffffffu, acc[j], off);
    if (lane == 0) {
        *(float4*)&g_as2[n * 4] = make_float4(acc[0], acc[1], acc[2], acc[3]);
        *(float4*)&g_ad2[n * 4] = make_float4(acc[4], acc[5], acc[6], acc[7]);
#pragma unroll
        for (int j = 0; j < 4; j++) atomicMax(&bmax[j], enc_f(acc[j]));
    }
    __syncthreads();
    if (threadIdx.x < 4) atomicMax(&g_gmax2[threadIdx.x], bmax[threadIdx.x]);
}

// ---------------- layer-2 aggregation over fp16 z (16 outputs per node) ----------------
__global__ void agg2_k(const __half* __restrict__ z, const int* __restrict__ gmax,
                       float* __restrict__ out) {
    __shared__ float ps[8][32][4];
    int n = (blockIdx.x * 256 + threadIdx.x) >> 5;
    int lane = threadIdx.x & 31;
    int w = threadIdx.x >> 5;
    int beg = g_rowptr[n], end = g_rowptr[n + 1];
    float4 ad4 = *(const float4*)&g_ad2[n * 4];
    float m0 = dec_f(gmax[0]) + ad4.x; m0 = fmaxf(m0, 0.2f * m0);
    float m1 = dec_f(gmax[1]) + ad4.y; m1 = fmaxf(m1, 0.2f * m1);
    float m2 = dec_f(gmax[2]) + ad4.z; m2 = fmaxf(m2, 0.2f * m2);
    float m3 = dec_f(gmax[3]) + ad4.w; m3 = fmaxf(m3, 0.2f * m3);

    float a0 = 0.f, a1 = 0.f;
    float s0 = 0.f, s1 = 0.f, s2 = 0.f, s3 = 0.f;
    int hd = lane >> 3;
    const __half* zp = z + 2 * lane;

    for (int base = beg; base < end; base += 32) {
        int i = base + lane;
        float p0 = 0.f, p1 = 0.f, p2 = 0.f, p3 = 0.f;
        int sj = 0;
        if (i < end) {
            sj = g_csr_src[i];
            float4 as4 = *(const float4*)&g_as2[sj * 4];
            float e;
            e = as4.x + ad4.x; e = fmaxf(e, 0.2f * e); p0 = __expf(e - m0);
            e = as4.y + ad4.y; e = fmaxf(e, 0.2f * e); p1 = __expf(e - m1);
            e = as4.z + ad4.z; e = fmaxf(e, 0.2f * e); p2 = __expf(e - m2);
            e = as4.w + ad4.w; e = fmaxf(e, 0.2f * e); p3 = __expf(e - m3);
        }
        s0 += p0; s1 += p1; s2 += p2; s3 += p3;
        ps[w][lane][0] = p0; ps[w][lane][1] = p1;
        ps[w][lane][2] = p2; ps[w][lane][3] = p3;
        __syncwarp();
        int cnt = min(32, end - base);
#pragma unroll 8
        for (int j = 0; j < cnt; j++) {
            int sc = __shfl_sync(0xffffffffu, sj, j);
            float p = ps[w][j][hd];
            float2 zv = __half22float2(*(const __half2*)(zp + (size_t)sc * 64));
            a0 += p * zv.x;
            a1 += p * zv.y;
        }
        __syncwarp();
    }
#pragma unroll
    for (int off = 16; off; off >>= 1) {
        s0 += __shfl_xor_sync(0xffffffffu, s0, off);
        s1 += __shfl_xor_sync(0xffffffffu, s1, off);
        s2 += __shfl_xor_sync(0xffffffffu, s2, off);
        s3 += __shfl_xor_sync(0xffffffffu, s3, off);
    }
    float sv = (hd == 0) ? s0 : (hd == 1) ? s1 : (hd == 2) ? s2 : s3;
    float inv = 0.25f / sv;      // folds head-mean
    a0 *= inv; a1 *= inv;
    a0 += __shfl_xor_sync(0xffffffffu, a0, 8);
    a1 += __shfl_xor_sync(0xffffffffu, a1, 8);
    a0 += __shfl_xor_sync(0xffffffffu, a0, 16);
    a1 += __shfl_xor_sync(0xffffffffu, a1, 16);
    if (lane < 8) {
        float2 cv = *(const float2*)&g_cvec[2 * lane];
        *(float2*)&out[n * 16 + 2 * lane] = make_float2(a0 + cv.x, a1 + cv.y);
    }
}

// ---------------- launch (single stream, 6 launches) ----------------
extern "C" void kernel_launch(void* const* d_in, const int* in_sizes, int n_in,
                              void* d_out, int out_size) {
    const float* x     = (const float*)d_in[0];
    const int*   ei    = (const int*)d_in[1];
    const float* W1    = (const float*)d_in[2];
    const float* atts1 = (const float*)d_in[3];
    const float* attd1 = (const float*)d_in[4];
    const float* b1    = (const float*)d_in[5];
    const float* W2    = (const float*)d_in[6];
    const float* atts2 = (const float*)d_in[7];
    const float* attd2 = (const float*)d_in[8];
    const float* b2    = (const float*)d_in[9];
    const float* Wout  = (const float*)d_in[10];
    const float* bout  = (const float*)d_in[11];
    float* out = (float*)d_out;

    __half* ghh;   cudaGetSymbolAddress((void**)&ghh, g_hh);
    __half* gxh;   cudaGetSymbolAddress((void**)&gxh, g_xh);
    __half* gx2h;  cudaGetSymbolAddress((void**)&gx2h, g_x2h);
    __half* gzh;   cudaGetSymbolAddress((void**)&gzh, g_zh);
    __half* gbt1;  cudaGetSymbolAddress((void**)&gbt1, g_bt1);
    __half* gbtz;  cudaGetSymbolAddress((void**)&gbtz, g_btz);
    float* gwsd1;  cudaGetSymbolAddress((void**)&gwsd1, g_wsd1);
    float* gwsd2;  cudaGetSymbolAddress((void**)&gwsd2, g_wsd2);
    int* ggm1;     cudaGetSymbolAddress((void**)&ggm1, g_gmax1);
    int* ggm2;     cudaGetSymbolAddress((void**)&ggm2, g_gmax2);

    prep_k<<<204, 256>>>(W1, atts1, attd1, W2, atts2, attd2, Wout, b2, bout);
    asad1_k<<<NN / 8, 256>>>(x, gwsd1, ei);

    // fused: scan + GEMM1 + scatter (overlapped in one launch)
    mid_k<<<MID_BLKS, 256>>>(gxh, gbt1, ghh, ei);

    agg1_k<<<NN / 8, 256>>>(ghh, b1, ggm1, gwsd2);

    gemmz_k<<<NNP / 128, 256>>>(gx2h, gbtz, gzh);   // z = x2 @ W2z (N=64, fp16)
    agg2_k<<<NN / 8, 256>>>(gzh, ggm2, out);
}